// round 8
// baseline (speedup 1.0000x reference)
#include <cuda_runtime.h>
#include <cuda_bf16.h>
#include <cstdint>

#define BATCH 2
#define CH 64
#define HW 4096   // 64*64

typedef unsigned long long u64;

__device__ __forceinline__ u64 pk2(float lo, float hi) {
    u64 r; asm("mov.b64 %0,{%1,%2};" : "=l"(r) : "f"(lo), "f"(hi)); return r;
}
__device__ __forceinline__ void upk2(u64 v, float& lo, float& hi) {
    asm("mov.b64 {%0,%1},%2;" : "=f"(lo), "=f"(hi) : "l"(v));
}
__device__ __forceinline__ u64 ffma2(u64 a, u64 b, u64 c) {
    u64 d; asm("fma.rn.f32x2 %0,%1,%2,%3;" : "=l"(d) : "l"(a), "l"(b), "l"(c)); return d;
}

// ---------------- scratch ----------------
__device__ float g_scale[4 * CH];
__device__ float g_xg[BATCH * CH * HW];
__device__ float g_gg[BATCH * CH * HW];
__device__ float g_xq[BATCH * CH * HW];
__device__ float g_gq[BATCH * CH * HW];
__device__ float g_xout[BATCH * CH * HW];
__device__ float g_gout[BATCH * CH * HW];
__device__ float g_outb[BATCH * CH * HW];
__device__ float g_t1[BATCH * CH * HW];
__device__ float g_sc[BATCH * CH * HW];
__device__ __nv_bfloat16 g_bkh[2 * BATCH * CH * HW];
__device__ __nv_bfloat16 g_bkl[2 * BATCH * CH * HW];
__device__ __nv_bfloat16 g_bvh[BATCH * CH * HW];
__device__ __nv_bfloat16 g_bvl[BATCH * CH * HW];

#define BUF_XG 0
#define BUF_GG 1
#define BUF_OUT 2
#define BUF_T1 3

#define BUF_SC 5
#define BUF_OT1 6

__device__ __forceinline__ float* pick_in(int w) {
    switch (w) {
        case BUF_XG: return g_xg;
        case BUF_GG: return g_gg;
        case BUF_OUT: return g_outb;
        default:     return g_t1;
    }
}
__device__ __forceinline__ float* pick_out(int w) {
    switch (w) {
        case BUF_SC: return g_sc;
        default:     return g_t1;
    }
}

// ================= helpers =================
__device__ __forceinline__ uint32_t su32(const void* p) {
    uint32_t a;
    asm("{ .reg .u64 t; cvta.to.shared.u64 t, %1; cvt.u32.u64 %0, t; }" : "=r"(a) : "l"(p));
    return a;
}
__device__ __forceinline__ void mma_bf16(float* d, const uint32_t* a, uint32_t b0, uint32_t b1) {
    asm volatile(
        "mma.sync.aligned.m16n8k16.row.col.f32.bf16.bf16.f32 "
        "{%0,%1,%2,%3}, {%4,%5,%6,%7}, {%8,%9}, {%0,%1,%2,%3};"
        : "+f"(d[0]), "+f"(d[1]), "+f"(d[2]), "+f"(d[3])
        : "r"(a[0]), "r"(a[1]), "r"(a[2]), "r"(a[3]), "r"(b0), "r"(b1));
}
__device__ __forceinline__ void ldsm4(uint32_t* r, uint32_t addr) {
    asm volatile("ldmatrix.sync.aligned.m8n8.x4.shared.b16 {%0,%1,%2,%3}, [%4];"
                 : "=r"(r[0]), "=r"(r[1]), "=r"(r[2]), "=r"(r[3]) : "r"(addr));
}
__device__ __forceinline__ void ldsm4t(uint32_t* r, uint32_t addr) {
    asm volatile("ldmatrix.sync.aligned.m8n8.x4.trans.shared.b16 {%0,%1,%2,%3}, [%4];"
                 : "=r"(r[0]), "=r"(r[1]), "=r"(r[2]), "=r"(r[3]) : "r"(addr));
}
__device__ __forceinline__ uint32_t cvt_bf2(float lo, float hi) {
    uint32_t r;
    asm("cvt.rn.bf16x2.f32 %0, %1, %2;" : "=r"(r) : "f"(hi), "f"(lo));
    return r;
}
__device__ __forceinline__ void split2(float a, float b, uint32_t& hw, uint32_t& lw) {
    uint32_t h = cvt_bf2(a, b);
    float ra = a - __uint_as_float(h << 16);
    float rb = b - __uint_as_float(h & 0xFFFF0000u);
    hw = h;
    lw = cvt_bf2(ra, rb);
}
__device__ __forceinline__ void wrb(__nv_bfloat16* H, __nv_bfloat16* L, int idx, float v) {
    __nv_bfloat16 h = __float2bfloat16_rn(v);
    H[idx] = h;
    L[idx] = __float2bfloat16_rn(v - __bfloat162float(h));
}
__device__ __forceinline__ void cpa16(uint32_t dst, const void* src) {
    asm volatile("cp.async.cg.shared.global [%0], [%1], 16;" :: "r"(dst), "l"(src) : "memory");
}
#define CPA_COMMIT() asm volatile("cp.async.commit_group;" ::: "memory")
#define CPA_WAIT1()  asm volatile("cp.async.wait_group 1;" ::: "memory")
#define CPA_WAIT0()  asm volatile("cp.async.wait_group 0;" ::: "memory")

// ---------------- 1. channel attention scalars ----------------
__global__ void kstats(const float* __restrict__ x, const float* __restrict__ g,
                       const float* __restrict__ lw, const float* __restrict__ lb) {
    int idx = blockIdx.x;
    int t = idx >> 7, b = (idx >> 6) & 1, c = idx & 63;
    const float* in = (t ? g : x) + (b * CH + c) * HW;
    float s = 0.f;
    for (int i = threadIdx.x; i < HW; i += 256) s += in[i];
    __shared__ float red[8];
    #pragma unroll
    for (int o = 16; o > 0; o >>= 1) s += __shfl_xor_sync(0xffffffffu, s, o);
    if ((threadIdx.x & 31) == 0) red[threadIdx.x >> 5] = s;
    __syncthreads();
    if (threadIdx.x == 0) {
        float tot = 0.f;
        #pragma unroll
        for (int i = 0; i < 8; i++) tot += red[i];
        float p = tot * (1.0f / (float)HW);
        float W = lw[0], B = lb[0];
        float h = p * W + B;
        h = h > 0.f ? h : 0.1f * h;
        float z = h * W + B;
        g_scale[idx] = 1.f / (1.f + expf(-z));
    }
}

// ---------------- 2. gated coord conv: 4 oc per block, f32x2 ----------------
__global__ void __launch_bounds__(256) kgated(const float* __restrict__ xin,
                                              const float* __restrict__ gin,
                                              const float* __restrict__ cw) {
    int z = blockIdx.z;
    int t = z >> 1, b = z & 1;
    const float* in = (t ? gin : xin) + b * CH * HW;
    float* out = (t ? g_gg : g_xg) + b * CH * HW;
    int ocg = blockIdx.y;

    __shared__ u64 ws2[4 * 594];
    for (int i = threadIdx.x; i < 4 * 594; i += 256) {
        int o = i / 594, r = i % 594;
        float w = cw[(ocg * 4 + o) * 594 + r];
        ws2[o * 594 + r] = pk2(w, w);
    }
    __syncthreads();

    int p = blockIdx.x * 1024 + threadIdx.x * 4;
    int row = p >> 6, col0 = p & 63;
    u64 acc2[4][2];
    #pragma unroll
    for (int o = 0; o < 4; o++) { acc2[o][0] = 0ULL; acc2[o][1] = 0ULL; }

    for (int ic = 0; ic < 64; ic++) {
        const float* ch = in + ic * HW;
        #pragma unroll
        for (int kh = 0; kh < 3; kh++) {
            int hh = row + kh - 1;
            if ((unsigned)hh >= 64u) continue;
            float v[6];
            #pragma unroll
            for (int u = 0; u < 6; u++) {
                int cc = col0 - 1 + u;
                v[u] = ((unsigned)cc < 64u) ? ch[hh * 64 + cc] : 0.f;
            }
            u64 p01 = pk2(v[0], v[1]), p12 = pk2(v[1], v[2]), p23 = pk2(v[2], v[3]);
            u64 p34 = pk2(v[3], v[4]), p45 = pk2(v[4], v[5]);
            #pragma unroll
            for (int o = 0; o < 4; o++) {
                const u64* wr = &ws2[o * 594 + ic * 9 + kh * 3];
                acc2[o][0] = ffma2(wr[0], p01, acc2[o][0]);
                acc2[o][1] = ffma2(wr[0], p23, acc2[o][1]);
                acc2[o][0] = ffma2(wr[1], p12, acc2[o][0]);
                acc2[o][1] = ffma2(wr[1], p34, acc2[o][1]);
                acc2[o][0] = ffma2(wr[2], p23, acc2[o][0]);
                acc2[o][1] = ffma2(wr[2], p45, acc2[o][1]);
            }
        }
    }
    // coord channels
    #pragma unroll
    for (int ic = 64; ic < 66; ic++) {
        #pragma unroll
        for (int kh = 0; kh < 3; kh++) {
            int hh = row + kh - 1;
            if ((unsigned)hh >= 64u) continue;
            float yyv = (float)hh * (2.f / 63.f) - 1.f;
            float v[6];
            #pragma unroll
            for (int u = 0; u < 6; u++) {
                int cc = col0 - 1 + u;
                float val = 0.f;
                if ((unsigned)cc < 64u)
                    val = (ic == 64) ? ((float)cc * (2.f / 63.f) - 1.f) : yyv;
                v[u] = val;
            }
            u64 p01 = pk2(v[0], v[1]), p12 = pk2(v[1], v[2]), p23 = pk2(v[2], v[3]);
            u64 p34 = pk2(v[3], v[4]), p45 = pk2(v[4], v[5]);
            #pragma unroll
            for (int o = 0; o < 4; o++) {
                const u64* wr = &ws2[o * 594 + ic * 9 + kh * 3];
                acc2[o][0] = ffma2(wr[0], p01, acc2[o][0]);
                acc2[o][1] = ffma2(wr[0], p23, acc2[o][1]);
                acc2[o][0] = ffma2(wr[1], p12, acc2[o][0]);
                acc2[o][1] = ffma2(wr[1], p34, acc2[o][1]);
                acc2[o][0] = ffma2(wr[2], p23, acc2[o][0]);
                acc2[o][1] = ffma2(wr[2], p45, acc2[o][1]);
            }
        }
    }

    #pragma unroll
    for (int o = 0; o < 4; o++) {
        int oc = ocg * 4 + o;
        float s = g_scale[z * CH + oc];
        float a0, a1, a2, a3;
        upk2(acc2[o][0], a0, a1);
        upk2(acc2[o][1], a2, a3);
        *(float4*)(out + oc * HW + p) = make_float4(s * a0, s * a1, s * a2, s * a3);
    }
}

// ---------------- 3. fused QKV projections; K/V written as bf16 hi/lo ----------------
__global__ void __launch_bounds__(128) kproj(
    const float* __restrict__ xq_w, const float* __restrict__ xq_b,
    const float* __restrict__ xk_w, const float* __restrict__ xk_b,
    const float* __restrict__ xv_w, const float* __restrict__ xv_b,
    const float* __restrict__ gq_w, const float* __restrict__ gq_b,
    const float* __restrict__ gk_w, const float* __restrict__ gk_b) {
    __shared__ float si[64 * 128];
    __shared__ float swt[3 * 512];
    __shared__ float sb2[3 * 8];

    int z = blockIdx.z;
    int side = z >> 1, b = z & 1;
    int og = blockIdx.y;
    int n0 = blockIdx.x * 128;
    int tid = threadIdx.x;

    const float* in = (side ? g_gg : g_xg) + b * CH * HW;
    const float* ws[3];
    const float* bs[3];
    int nset;
    if (side == 0) {
        ws[0] = xq_w; ws[1] = xk_w; ws[2] = xv_w;
        bs[0] = xq_b; bs[1] = xk_b; bs[2] = xv_b;
        nset = 3;
    } else {
        ws[0] = gq_w; ws[1] = gk_w; ws[2] = gk_w;
        bs[0] = gq_b; bs[1] = gk_b; bs[2] = gk_b;
        nset = 2;
    }

    for (int i = tid; i < 2048; i += 128) {
        int c = i >> 5, p4 = (i & 31) * 4;
        *(float4*)(si + c * 128 + p4) = *(const float4*)(in + c * HW + n0 + p4);
    }
    for (int s = 0; s < nset; s++) {
        for (int i = tid; i < 512; i += 128) {
            int c = i >> 3, o = i & 7;
            swt[s * 512 + c * 8 + o] = ws[s][(og * 8 + o) * 64 + c];
        }
        if (tid < 8) sb2[s * 8 + tid] = bs[s][og * 8 + tid];
    }
    __syncthreads();

    u64 acc[3][4];
    #pragma unroll
    for (int s = 0; s < 3; s++)
        #pragma unroll
        for (int k = 0; k < 4; k++)
            acc[s][k] = pk2(sb2[s * 8 + 2 * k], sb2[s * 8 + 2 * k + 1]);

    if (side == 0) {
        for (int c = 0; c < 64; c++) {
            float iv = si[c * 128 + tid];
            u64 ivp = pk2(iv, iv);
            #pragma unroll
            for (int s = 0; s < 3; s++) {
                ulonglong2 wa = *(const ulonglong2*)(swt + s * 512 + c * 8);
                ulonglong2 wb = *(const ulonglong2*)(swt + s * 512 + c * 8 + 4);
                acc[s][0] = ffma2(ivp, wa.x, acc[s][0]);
                acc[s][1] = ffma2(ivp, wa.y, acc[s][1]);
                acc[s][2] = ffma2(ivp, wb.x, acc[s][2]);
                acc[s][3] = ffma2(ivp, wb.y, acc[s][3]);
            }
        }
    } else {
        for (int c = 0; c < 64; c++) {
            float iv = si[c * 128 + tid];
            u64 ivp = pk2(iv, iv);
            #pragma unroll
            for (int s = 0; s < 2; s++) {
                ulonglong2 wa = *(const ulonglong2*)(swt + s * 512 + c * 8);
                ulonglong2 wb = *(const ulonglong2*)(swt + s * 512 + c * 8 + 4);
                acc[s][0] = ffma2(ivp, wa.x, acc[s][0]);
                acc[s][1] = ffma2(ivp, wa.y, acc[s][1]);
                acc[s][2] = ffma2(ivp, wb.x, acc[s][2]);
                acc[s][3] = ffma2(ivp, wb.y, acc[s][3]);
            }
        }
    }

    float* qdst = side ? g_gq : g_xq;
    __nv_bfloat16* KhD = g_bkh + (long)side * BATCH * CH * HW;
    __nv_bfloat16* KlD = g_bkl + (long)side * BATCH * CH * HW;
    #pragma unroll
    for (int k = 0; k < 4; k++) {
        int i0 = (b * CH + og * 8 + 2 * k) * HW + n0 + tid;
        float lo, hi;
        upk2(acc[0][k], lo, hi);
        qdst[i0] = lo; qdst[i0 + HW] = hi;
        upk2(acc[1][k], lo, hi);
        wrb(KhD, KlD, i0, lo); wrb(KhD, KlD, i0 + HW, hi);
        if (side == 0) {
            upk2(acc[2][k], lo, hi);
            wrb(g_bvh, g_bvl, i0, lo); wrb(g_bvh, g_bvl, i0 + HW, hi);
        }
    }
}

// ---------------- 4. flash attention: mma.sync, split accumulator chains ----------------
// grid (64, B, 2), block 128 = 4 warps. CTA: 64 Q-rows; warp: 16 rows.
__global__ void __launch_bounds__(128) kattn() {
    extern __shared__ __align__(16) uint8_t dyn[];

    const int tid = threadIdx.x;
    const int lane = tid & 31, wid = tid >> 5;
    const int tg = lane & 3, g = lane >> 2;
    const int b = blockIdx.y, kind = blockIdx.z;
    const int n0 = blockIdx.x * 64;
    const float* Qp = (kind ? g_gq : g_xq) + b * CH * HW;
    const __nv_bfloat16* Kh = g_bkh + ((long)kind * BATCH + b) * CH * HW;
    const __nv_bfloat16* Kl = g_bkl + ((long)kind * BATCH + b) * CH * HW;
    const __nv_bfloat16* Vh = g_bvh + (long)b * CH * HW;
    const __nv_bfloat16* Vl = g_bvl + (long)b * CH * HW;
    float* Op = (kind ? g_gout : g_xout) + b * CH * HW;

    const uint32_t sb = su32(dyn);

    // ---- stage Q (hi/lo), load A-frags ----
    {
        __nv_bfloat16* Qh = (__nv_bfloat16*)dyn;
        __nv_bfloat16* Ql = (__nv_bfloat16*)(dyn + 9216);
        for (int idx = tid; idx < 4096; idx += 128) {
            int i = idx & 63, c = idx >> 6;
            float a = Qp[c * HW + n0 + i];
            __nv_bfloat16 h = __float2bfloat16_rn(a);
            Qh[i * 72 + c] = h;
            Ql[i * 72 + c] = __float2bfloat16_rn(a - __bfloat162float(h));
        }
    }
    __syncthreads();

    uint32_t qh[4][4], ql[4][4];
    {
        int rl = lane & 15, ca = (lane >> 4) << 3;
        #pragma unroll
        for (int kc = 0; kc < 4; kc++) {
            uint32_t off = (uint32_t)(((16 * wid + rl) * 72 + 16 * kc + ca) * 2);
            ldsm4(qh[kc], sb + off);
            ldsm4(ql[kc], sb + 9216 + off);
        }
    }
    __syncthreads();

    float ohi[8][4], omx[8][4];
    #pragma unroll
    for (int cb = 0; cb < 8; cb++)
        #pragma unroll
        for (int r = 0; r < 4; r++) { ohi[cb][r] = 0.f; omx[cb][r] = 0.f; }
    float mrow0 = -1e30f, mrow1 = -1e30f, lrow0 = 0.f, lrow1 = 0.f;

    const uint32_t k_off = (uint32_t)(((lane & 15) * 72 + ((lane >> 4) << 3)) * 2);
    const uint32_t v_off = (uint32_t)(((((lane >> 4) << 3) + (lane & 7)) * 72 +
                                      (((lane >> 3) & 1) << 3)) * 2);

    // prefetch tile 0 into buf0
    {
        #pragma unroll
        for (int u = 0; u < 4; u++) {
            int i = tid + u * 128;
            int row = i >> 3, ch = i & 7;
            uint32_t dst = sb + row * 144 + ch * 16;
            long go = (long)row * HW + ch * 8;
            cpa16(dst,          Kh + go);
            cpa16(dst + 9216,   Kl + go);
            cpa16(dst + 18432,  Vh + go);
            cpa16(dst + 27648,  Vl + go);
        }
        CPA_COMMIT();
    }

    for (int kt = 0; kt < 64; kt++) {
        const uint32_t bufc = sb + (uint32_t)(kt & 1) * 36864;

        if (kt < 63) {
            uint32_t bufn = sb + (uint32_t)((kt + 1) & 1) * 36864;
            int m0n = (kt + 1) * 64;
            #pragma unroll
            for (int u = 0; u < 4; u++) {
                int i = tid + u * 128;
                int row = i >> 3, ch = i & 7;
                uint32_t dst = bufn + row * 144 + ch * 16;
                long go = (long)row * HW + m0n + ch * 8;
                cpa16(dst,          Kh + go);
                cpa16(dst + 9216,   Kl + go);
                cpa16(dst + 18432,  Vh + go);
                cpa16(dst + 27648,  Vl + go);
            }
            CPA_COMMIT();
            CPA_WAIT1();
        } else {
            CPA_WAIT0();
        }
        __syncthreads();

        // ---- S = Q K^T : hi-chain (sh) + mix-chain (smx), distance-4 scheduling ----
        float sh[8][4], smx[8][4];
        #pragma unroll
        for (int nb = 0; nb < 8; nb++)
            #pragma unroll
            for (int r = 0; r < 4; r++) { sh[nb][r] = 0.f; smx[nb][r] = 0.f; }

        #pragma unroll
        for (int kc = 0; kc < 4; kc++) {
            #pragma unroll
            for (int jp = 0; jp < 2; jp++) {         // jb pairs (0,1), (2,3)
                int j0 = 2 * jp, j1 = 2 * jp + 1;
                uint32_t bh0[4], bl0[4], bh1[4], bl1[4];
                uint32_t t0 = (uint32_t)((kc * 16 * 72 + j0 * 16) * 2);
                uint32_t t1 = (uint32_t)((kc * 16 * 72 + j1 * 16) * 2);
                ldsm4t(bh0, bufc + k_off + t0);
                ldsm4t(bl0, bufc + 9216 + k_off + t0);
                ldsm4t(bh1, bufc + k_off + t1);
                ldsm4t(bl1, bufc + 9216 + k_off + t1);
                mma_bf16(sh[2 * j0],      qh[kc], bh0[0], bh0[1]);
                mma_bf16(sh[2 * j0 + 1],  qh[kc], bh0[2], bh0[3]);
                mma_bf16(sh[2 * j1],      qh[kc], bh1[0], bh1[1]);
                mma_bf16(sh[2 * j1 + 1],  qh[kc], bh1[2], bh1[3]);
                mma_bf16(smx[2 * j0],     qh[kc], bl0[0], bl0[1]);
                mma_bf16(smx[2 * j0 + 1], qh[kc], bl0[2], bl0[3]);
                mma_bf16(smx[2 * j1],     qh[kc], bl1[0], bl1[1]);
                mma_bf16(smx[2 * j1 + 1], qh[kc], bl1[2], bl1[3]);
                mma_bf16(smx[2 * j0],     ql[kc], bh0[0], bh0[1]);
                mma_bf16(smx[2 * j0 + 1], ql[kc], bh0[2], bh0[3]);
                mma_bf16(smx[2 * j1],     ql[kc], bh1[0], bh1[1]);
                mma_bf16(smx[2 * j1 + 1], ql[kc], bh1[2], bh1[3]);
            }
        }
        float sa[8][4];
        #pragma unroll
        for (int nb = 0; nb < 8; nb++)
            #pragma unroll
            for (int r = 0; r < 4; r++) sa[nb][r] = sh[nb][r] + smx[nb][r];

        // ---- online softmax ----
        float tm0 = -1e30f, tm1 = -1e30f;
        #pragma unroll
        for (int nb = 0; nb < 8; nb++) {
            tm0 = fmaxf(tm0, fmaxf(sa[nb][0], sa[nb][1]));
            tm1 = fmaxf(tm1, fmaxf(sa[nb][2], sa[nb][3]));
        }
        tm0 = fmaxf(tm0, __shfl_xor_sync(0xffffffffu, tm0, 1));
        tm0 = fmaxf(tm0, __shfl_xor_sync(0xffffffffu, tm0, 2));
        tm1 = fmaxf(tm1, __shfl_xor_sync(0xffffffffu, tm1, 1));
        tm1 = fmaxf(tm1, __shfl_xor_sync(0xffffffffu, tm1, 2));
        float mn0 = fmaxf(mrow0, tm0), mn1 = fmaxf(mrow1, tm1);
        float corr0 = __expf(mrow0 - mn0), corr1 = __expf(mrow1 - mn1);
        mrow0 = mn0; mrow1 = mn1;

        float ps0 = 0.f, ps1 = 0.f;
        #pragma unroll
        for (int nb = 0; nb < 8; nb++) {
            sa[nb][0] = __expf(sa[nb][0] - mn0);
            sa[nb][1] = __expf(sa[nb][1] - mn0);
            sa[nb][2] = __expf(sa[nb][2] - mn1);
            sa[nb][3] = __expf(sa[nb][3] - mn1);
            ps0 += sa[nb][0] + sa[nb][1];
            ps1 += sa[nb][2] + sa[nb][3];
        }
        ps0 += __shfl_xor_sync(0xffffffffu, ps0, 1);
        ps0 += __shfl_xor_sync(0xffffffffu, ps0, 2);
        ps1 += __shfl_xor_sync(0xffffffffu, ps1, 1);
        ps1 += __shfl_xor_sync(0xffffffffu, ps1, 2);
        lrow0 = lrow0 * corr0 + ps0;
        lrow1 = lrow1 * corr1 + ps1;

        #pragma unroll
        for (int cb = 0; cb < 8; cb++) {
            ohi[cb][0] *= corr0; ohi[cb][1] *= corr0;
            ohi[cb][2] *= corr1; ohi[cb][3] *= corr1;
            omx[cb][0] *= corr0; omx[cb][1] *= corr0;
            omx[cb][2] *= corr1; omx[cb][3] *= corr1;
        }

        // ---- P a-frags (hi/lo) ----
        uint32_t ph[4][4], pl[4][4];
        #pragma unroll
        for (int kc = 0; kc < 4; kc++) {
            split2(sa[2 * kc][0],     sa[2 * kc][1],     ph[kc][0], pl[kc][0]);
            split2(sa[2 * kc][2],     sa[2 * kc][3],     ph[kc][1], pl[kc][1]);
            split2(sa[2 * kc + 1][0], sa[2 * kc + 1][1], ph[kc][2], pl[kc][2]);
            split2(sa[2 * kc + 1][2], sa[2 * kc + 1][3], ph[kc][3], pl[kc][3]);
        }

        // ---- O += P V^T : hi-chain (ohi) + mix-chain (omx), distance-4 ----
        #pragma unroll
        for (int kc = 0; kc < 4; kc++) {
            #pragma unroll
            for (int cpp = 0; cpp < 2; cpp++) {      // cp pairs (0,1), (2,3)
                int c0 = 2 * cpp, c1 = 2 * cpp + 1;
                uint32_t bh0[4], bl0[4], bh1[4], bl1[4];
                uint32_t t0 = (uint32_t)((c0 * 16 * 72 + kc * 16) * 2);
                uint32_t t1 = (uint32_t)((c1 * 16 * 72 + kc * 16) * 2);
                ldsm4(bh0, bufc + 18432 + v_off + t0);
                ldsm4(bl0, bufc + 27648 + v_off + t0);
                ldsm4(bh1, bufc + 18432 + v_off + t1);
                ldsm4(bl1, bufc + 27648 + v_off + t1);
                mma_bf16(ohi[2 * c0],     ph[kc], bh0[0], bh0[1]);
                mma_bf16(ohi[2 * c0 + 1], ph[kc], bh0[2], bh0[3]);
                mma_bf16(ohi[2 * c1],     ph[kc], bh1[0], bh1[1]);
                mma_bf16(ohi[2 * c1 + 1], ph[kc], bh1[2], bh1[3]);
                mma_bf16(omx[2 * c0],     ph[kc], bl0[0], bl0[1]);
                mma_bf16(omx[2 * c0 + 1], ph[kc], bl0[2], bl0[3]);
                mma_bf16(omx[2 * c1],     ph[kc], bl1[0], bl1[1]);
                mma_bf16(omx[2 * c1 + 1], ph[kc], bl1[2], bl1[3]);
                mma_bf16(omx[2 * c0],     pl[kc], bh0[0], bh0[1]);
                mma_bf16(omx[2 * c0 + 1], pl[kc], bh0[2], bh0[3]);
                mma_bf16(omx[2 * c1],     pl[kc], bh1[0], bh1[1]);
                mma_bf16(omx[2 * c1 + 1], pl[kc], bh1[2], bh1[3]);
            }
        }
        __syncthreads();
    }

    // ---- epilogue ----
    float inv0 = 1.f / lrow0, inv1 = 1.f / lrow1;
    int i0 = n0 + 16 * wid + g;
    #pragma unroll
    for (int cb = 0; cb < 8; cb++) {
        int c = 8 * cb + 2 * tg;
        Op[c * HW + i0]           = (ohi[cb][0] + omx[cb][0]) * inv0;
        Op[(c + 1) * HW + i0]     = (ohi[cb][1] + omx[cb][1]) * inv0;
        Op[c * HW + i0 + 8]       = (ohi[cb][2] + omx[cb][2]) * inv1;
        Op[(c + 1) * HW + i0 + 8] = (ohi[cb][3] + omx[cb][3]) * inv1;
    }
}

// ---------------- 5. combine ----------------
__global__ void kcombine(const float* __restrict__ gamma, const float* __restrict__ alpha) {
    int i = blockIdx.x * 256 + threadIdx.x;
    g_outb[i] = gamma[0] * g_xout[i] + alpha[0] * g_gout[i];
}

// ---------------- 6. plain conv3x3: 4 oc per block, f32x2, optional fused final ----------------
__global__ void __launch_bounds__(256) kconv3(const float* __restrict__ w,
                                              const float* __restrict__ bias,
                                              int in_id, int out_id, int leaky_in,
                                              int finalize, float* __restrict__ dout) {
    const float* inb = pick_in(in_id);
    int b = blockIdx.z, ocg = blockIdx.y;

    __shared__ u64 ws2[4 * 576];
    for (int i = threadIdx.x; i < 4 * 576; i += 256) {
        int o = i / 576, r = i % 576;
        float wv = w[(ocg * 4 + o) * 576 + r];
        ws2[o * 576 + r] = pk2(wv, wv);
    }
    __syncthreads();

    int p = blockIdx.x * 1024 + threadIdx.x * 4;
    int row = p >> 6, col0 = p & 63;
    u64 acc2[4][2];
    #pragma unroll
    for (int o = 0; o < 4; o++) {
        float bv = bias[ocg * 4 + o];
        acc2[o][0] = pk2(bv, bv);
        acc2[o][1] = pk2(bv, bv);
    }
    const float* in = inb + b * CH * HW;

    for (int ic = 0; ic < 64; ic++) {
        const float* ch = in + ic * HW;
        #pragma unroll
        for (int kh = 0; kh < 3; kh++) {
            int hh = row + kh - 1;
            if ((unsigned)hh >= 64u) continue;
            float v[6];
            #pragma unroll
            for (int u = 0; u < 6; u++) {
                int cc = col0 - 1 + u;
                float val = ((unsigned)cc < 64u) ? ch[hh * 64 + cc] : 0.f;
                if (leaky_in) val = val > 0.f ? val : 0.1f * val;
                v[u] = val;
            }
            u64 p01 = pk2(v[0], v[1]), p12 = pk2(v[1], v[2]), p23 = pk2(v[2], v[3]);
            u64 p34 = pk2(v[3], v[4]), p45 = pk2(v[4], v[5]);
            #pragma unroll
            for (int o = 0; o < 4; o++) {
                const u64* wr = &ws2[o * 576 + ic * 9 + kh * 3];
                acc2[o][0] = ffma2(wr[0], p01, acc2[o][0]);
                acc2[o][1] = ffma2(wr[0], p23, acc2[o][1]);
                acc2[o][0] = ffma2(wr[1], p12, acc2[o][0]);
                acc2[o][1] = ffma2(wr[1], p34, acc2[o][1]);
                acc2[o][0] = ffma2(wr[2], p23, acc2[o][0]);
                acc2[o][1] = ffma2(wr[2], p45, acc2[o][1]);
            }
        }
    }
    if (finalize) {
        #pragma unroll
        for (int o = 0; o < 4; o++) {
            int base = (b * CH + ocg * 4 + o) * HW + p;
            float4 scv = *(const float4*)(g_sc + base);
            float4 gov = *(const float4*)(g_gout + base);
            float a0, a1, a2, a3;
            upk2(acc2[o][0], a0, a1);
            upk2(acc2[o][1], a2, a3);
            *(float4*)(dout + base) = make_float4(a0 + scv.x * gov.x,
                                                  a1 + scv.y * gov.y,
                                                  a2 + scv.z * gov.z,
                                                  a3 + scv.w * gov.w);
        }
    } else {
        float* outb = pick_out(out_id);
        #pragma unroll
        for (int o = 0; o < 4; o++) {
            float* op = outb + (b * CH + ocg * 4 + o) * HW + p;
            float a0, a1, a2, a3;
            upk2(acc2[o][0], a0, a1);
            upk2(acc2[o][1], a2, a3);
            *(float4*)op = make_float4(a0, a1, a2, a3);
        }
    }
}

// ---------------- 3b. 1x1 conv (shortcut path) ----------------
__global__ void k1x1(const float* __restrict__ w, const float* __restrict__ bias,
                     int in_id, int out_id) {
    const float* in = pick_in(in_id);
    float* out = pick_out(out_id);
    int b = blockIdx.z, og = blockIdx.y;
    int n0 = blockIdx.x * 128;

    __shared__ float si[64 * 128];
    __shared__ float sw[8 * 64];
    for (int i = threadIdx.x; i < 64 * 128; i += 128) {
        int c = i >> 7, px = i & 127;
        si[i] = in[(b * CH + c) * HW + n0 + px];
    }
    for (int i = threadIdx.x; i < 512; i += 128)
        sw[i] = w[(og * 8 + (i >> 6)) * 64 + (i & 63)];
    __syncthreads();

    float acc[8];
    #pragma unroll
    for (int o = 0; o < 8; o++) acc[o] = bias[og * 8 + o];
    for (int c = 0; c < 64; c++) {
        float iv = si[c * 128 + threadIdx.x];
        #pragma unroll
        for (int o = 0; o < 8; o++) acc[o] += sw[o * 64 + c] * iv;
    }
    #pragma unroll
    for (int o = 0; o < 8; o++)
        out[(b * CH + og * 8 + o) * HW + n0 + threadIdx.x] = acc[o];
}

extern "C" void kernel_launch(void* const* d_in, const int* in_sizes, int n_in,
                              void* d_out, int out_size) {
    const float* x       = (const float*)d_in[0];
    const float* guide   = (const float*)d_in[1];
    const float* lin_w   = (const float*)d_in[2];
    const float* lin_b   = (const float*)d_in[3];
    const float* coord_w = (const float*)d_in[4];
    const float* xq_w = (const float*)d_in[5];
    const float* xq_b = (const float*)d_in[6];
    const float* xk_w = (const float*)d_in[7];
    const float* xk_b = (const float*)d_in[8];
    const float* xv_w = (const float*)d_in[9];
    const float* xv_b = (const float*)d_in[10];
    const float* gq_w = (const float*)d_in[11];
    const float* gq_b = (const float*)d_in[12];
    const float* gk_w = (const float*)d_in[13];
    const float* gk_b = (const float*)d_in[14];
    const float* gamma = (const float*)d_in[15];
    const float* alpha = (const float*)d_in[16];
    const float* c1_w = (const float*)d_in[17];
    const float* c1_b = (const float*)d_in[18];
    const float* c2_w = (const float*)d_in[19];
    const float* c2_b = (const float*)d_in[20];
    const float* sc_w = (const float*)d_in[21];
    const float* sc_b = (const float*)d_in[22];
    float* out = (float*)d_out;

    cudaFuncSetAttribute(kattn, cudaFuncAttributeMaxDynamicSharedMemorySize, 73728);

    kstats<<<256, 256>>>(x, guide, lin_w, lin_b);
    kgated<<<dim3(4, 16, 4), 256>>>(x, guide, coord_w);

    kproj<<<dim3(32, 8, 4), 128>>>(xq_w, xq_b, xk_w, xk_b, xv_w, xv_b,
                                   gq_w, gq_b, gk_w, gk_b);

    kattn<<<dim3(64, BATCH, 2), 128, 73728>>>();

    kcombine<<<2048, 256>>>(gamma, alpha);

    kconv3<<<dim3(4, 16, BATCH), 256>>>(c1_w, c1_b, BUF_OUT, BUF_OT1, 1, 0, nullptr);
    k1x1<<<dim3(32, 8, BATCH), 128>>>(sc_w, sc_b, BUF_OUT, BUF_SC);
    kconv3<<<dim3(4, 16, BATCH), 256>>>(c2_w, c2_b, BUF_T1, 0, 1, 1, out);
}

// round 9
// speedup vs baseline: 1.1226x; 1.1226x over previous
#include <cuda_runtime.h>
#include <cuda_bf16.h>
#include <cstdint>

#define BATCH 2
#define CH 64
#define HW 4096   // 64*64

typedef unsigned long long u64;

__device__ __forceinline__ u64 pk2(float lo, float hi) {
    u64 r; asm("mov.b64 %0,{%1,%2};" : "=l"(r) : "f"(lo), "f"(hi)); return r;
}
__device__ __forceinline__ void upk2(u64 v, float& lo, float& hi) {
    asm("mov.b64 {%0,%1},%2;" : "=f"(lo), "=f"(hi) : "l"(v));
}
__device__ __forceinline__ u64 ffma2(u64 a, u64 b, u64 c) {
    u64 d; asm("fma.rn.f32x2 %0,%1,%2,%3;" : "=l"(d) : "l"(a), "l"(b), "l"(c)); return d;
}

// ---------------- scratch ----------------
__device__ float g_scale[4 * CH];
__device__ float g_xg[BATCH * CH * HW];
__device__ float g_gg[BATCH * CH * HW];
__device__ float g_xq[BATCH * CH * HW];
__device__ float g_gq[BATCH * CH * HW];
__device__ float g_xout[BATCH * CH * HW];
__device__ float g_gout[BATCH * CH * HW];
__device__ float g_outb[BATCH * CH * HW];
__device__ float g_t1[BATCH * CH * HW];
__device__ float g_sc[BATCH * CH * HW];
__device__ __nv_bfloat16 g_bkh[2 * BATCH * CH * HW];
__device__ __nv_bfloat16 g_bkl[2 * BATCH * CH * HW];
__device__ __nv_bfloat16 g_bvh[BATCH * CH * HW];
__device__ __nv_bfloat16 g_bvl[BATCH * CH * HW];
// split-KV partials: O [kind][b][split][c][hw], m/l [kind][b][split][hw]
__device__ float g_pO[2 * BATCH * 2 * CH * HW];
__device__ float g_pm[2 * BATCH * 2 * HW];
__device__ float g_pl[2 * BATCH * 2 * HW];

#define BUF_XG 0
#define BUF_GG 1
#define BUF_OUT 2
#define BUF_T1 3

#define BUF_SC 5
#define BUF_OT1 6

__device__ __forceinline__ float* pick_in(int w) {
    switch (w) {
        case BUF_XG: return g_xg;
        case BUF_GG: return g_gg;
        case BUF_OUT: return g_outb;
        default:     return g_t1;
    }
}
__device__ __forceinline__ float* pick_out(int w) {
    switch (w) {
        case BUF_SC: return g_sc;
        default:     return g_t1;
    }
}

// ================= helpers =================
__device__ __forceinline__ uint32_t su32(const void* p) {
    uint32_t a;
    asm("{ .reg .u64 t; cvta.to.shared.u64 t, %1; cvt.u32.u64 %0, t; }" : "=r"(a) : "l"(p));
    return a;
}
__device__ __forceinline__ void mma_bf16(float* d, const uint32_t* a, uint32_t b0, uint32_t b1) {
    asm volatile(
        "mma.sync.aligned.m16n8k16.row.col.f32.bf16.bf16.f32 "
        "{%0,%1,%2,%3}, {%4,%5,%6,%7}, {%8,%9}, {%0,%1,%2,%3};"
        : "+f"(d[0]), "+f"(d[1]), "+f"(d[2]), "+f"(d[3])
        : "r"(a[0]), "r"(a[1]), "r"(a[2]), "r"(a[3]), "r"(b0), "r"(b1));
}
__device__ __forceinline__ void ldsm4(uint32_t* r, uint32_t addr) {
    asm volatile("ldmatrix.sync.aligned.m8n8.x4.shared.b16 {%0,%1,%2,%3}, [%4];"
                 : "=r"(r[0]), "=r"(r[1]), "=r"(r[2]), "=r"(r[3]) : "r"(addr));
}
__device__ __forceinline__ void ldsm4t(uint32_t* r, uint32_t addr) {
    asm volatile("ldmatrix.sync.aligned.m8n8.x4.trans.shared.b16 {%0,%1,%2,%3}, [%4];"
                 : "=r"(r[0]), "=r"(r[1]), "=r"(r[2]), "=r"(r[3]) : "r"(addr));
}
__device__ __forceinline__ uint32_t cvt_bf2(float lo, float hi) {
    uint32_t r;
    asm("cvt.rn.bf16x2.f32 %0, %1, %2;" : "=r"(r) : "f"(hi), "f"(lo));
    return r;
}
__device__ __forceinline__ void split2(float a, float b, uint32_t& hw, uint32_t& lw) {
    uint32_t h = cvt_bf2(a, b);
    float ra = a - __uint_as_float(h << 16);
    float rb = b - __uint_as_float(h & 0xFFFF0000u);
    hw = h;
    lw = cvt_bf2(ra, rb);
}
__device__ __forceinline__ void wrb(__nv_bfloat16* H, __nv_bfloat16* L, int idx, float v) {
    __nv_bfloat16 h = __float2bfloat16_rn(v);
    H[idx] = h;
    L[idx] = __float2bfloat16_rn(v - __bfloat162float(h));
}
__device__ __forceinline__ void cpa16(uint32_t dst, const void* src) {
    asm volatile("cp.async.cg.shared.global [%0], [%1], 16;" :: "r"(dst), "l"(src) : "memory");
}
#define CPA_COMMIT() asm volatile("cp.async.commit_group;" ::: "memory")
#define CPA_WAIT1()  asm volatile("cp.async.wait_group 1;" ::: "memory")
#define CPA_WAIT0()  asm volatile("cp.async.wait_group 0;" ::: "memory")

// ---------------- 1. channel attention scalars ----------------
__global__ void kstats(const float* __restrict__ x, const float* __restrict__ g,
                       const float* __restrict__ lw, const float* __restrict__ lb) {
    int idx = blockIdx.x;
    int t = idx >> 7, b = (idx >> 6) & 1, c = idx & 63;
    const float* in = (t ? g : x) + (b * CH + c) * HW;
    float s = 0.f;
    for (int i = threadIdx.x; i < HW; i += 256) s += in[i];
    __shared__ float red[8];
    #pragma unroll
    for (int o = 16; o > 0; o >>= 1) s += __shfl_xor_sync(0xffffffffu, s, o);
    if ((threadIdx.x & 31) == 0) red[threadIdx.x >> 5] = s;
    __syncthreads();
    if (threadIdx.x == 0) {
        float tot = 0.f;
        #pragma unroll
        for (int i = 0; i < 8; i++) tot += red[i];
        float p = tot * (1.0f / (float)HW);
        float W = lw[0], B = lb[0];
        float h = p * W + B;
        h = h > 0.f ? h : 0.1f * h;
        float z = h * W + B;
        g_scale[idx] = 1.f / (1.f + expf(-z));
    }
}

// ---------------- 2. gated coord conv: 4 oc per block (R7 scalar form) ----------------
__global__ void __launch_bounds__(256) kgated(const float* __restrict__ xin,
                                              const float* __restrict__ gin,
                                              const float* __restrict__ cw) {
    int z = blockIdx.z;
    int t = z >> 1, b = z & 1;
    const float* in = (t ? gin : xin) + b * CH * HW;
    float* out = (t ? g_gg : g_xg) + b * CH * HW;
    int ocg = blockIdx.y;

    __shared__ float ws[4 * 66 * 9];
    for (int i = threadIdx.x; i < 4 * 594; i += 256) {
        int o = i / 594, r = i % 594;
        ws[o * 594 + r] = cw[(ocg * 4 + o) * 594 + r];
    }
    __syncthreads();

    int p = blockIdx.x * 1024 + threadIdx.x * 4;
    int row = p >> 6, col0 = p & 63;
    float acc[4][4];
    #pragma unroll
    for (int o = 0; o < 4; o++)
        #pragma unroll
        for (int u = 0; u < 4; u++) acc[o][u] = 0.f;

    for (int ic = 0; ic < 64; ic++) {
        const float* ch = in + ic * HW;
        #pragma unroll
        for (int kh = 0; kh < 3; kh++) {
            int hh = row + kh - 1;
            if ((unsigned)hh >= 64u) continue;
            float v[6];
            #pragma unroll
            for (int u = 0; u < 6; u++) {
                int cc = col0 - 1 + u;
                v[u] = ((unsigned)cc < 64u) ? ch[hh * 64 + cc] : 0.f;
            }
            #pragma unroll
            for (int o = 0; o < 4; o++) {
                const float* wr = &ws[o * 594 + ic * 9 + kh * 3];
                #pragma unroll
                for (int kw = 0; kw < 3; kw++) {
                    float wv = wr[kw];
                    acc[o][0] += wv * v[kw + 0];
                    acc[o][1] += wv * v[kw + 1];
                    acc[o][2] += wv * v[kw + 2];
                    acc[o][3] += wv * v[kw + 3];
                }
            }
        }
    }
    #pragma unroll
    for (int ic = 64; ic < 66; ic++) {
        #pragma unroll
        for (int kh = 0; kh < 3; kh++) {
            int hh = row + kh - 1;
            if ((unsigned)hh >= 64u) continue;
            float yyv = (float)hh * (2.f / 63.f) - 1.f;
            float v[6];
            #pragma unroll
            for (int u = 0; u < 6; u++) {
                int cc = col0 - 1 + u;
                float val = 0.f;
                if ((unsigned)cc < 64u)
                    val = (ic == 64) ? ((float)cc * (2.f / 63.f) - 1.f) : yyv;
                v[u] = val;
            }
            #pragma unroll
            for (int o = 0; o < 4; o++) {
                const float* wr = &ws[o * 594 + ic * 9 + kh * 3];
                #pragma unroll
                for (int kw = 0; kw < 3; kw++) {
                    float wv = wr[kw];
                    acc[o][0] += wv * v[kw + 0];
                    acc[o][1] += wv * v[kw + 1];
                    acc[o][2] += wv * v[kw + 2];
                    acc[o][3] += wv * v[kw + 3];
                }
            }
        }
    }

    #pragma unroll
    for (int o = 0; o < 4; o++) {
        int oc = ocg * 4 + o;
        float s = g_scale[z * CH + oc];
        float* op = out + oc * HW + p;
        *(float4*)op = make_float4(s * acc[o][0], s * acc[o][1], s * acc[o][2], s * acc[o][3]);
    }
}

// ---------------- 3. fused QKV projections; K/V written as bf16 hi/lo ----------------
__global__ void __launch_bounds__(128) kproj(
    const float* __restrict__ xq_w, const float* __restrict__ xq_b,
    const float* __restrict__ xk_w, const float* __restrict__ xk_b,
    const float* __restrict__ xv_w, const float* __restrict__ xv_b,
    const float* __restrict__ gq_w, const float* __restrict__ gq_b,
    const float* __restrict__ gk_w, const float* __restrict__ gk_b) {
    __shared__ float si[64 * 128];
    __shared__ float swt[3 * 512];
    __shared__ float sb2[3 * 8];

    int z = blockIdx.z;
    int side = z >> 1, b = z & 1;
    int og = blockIdx.y;
    int n0 = blockIdx.x * 128;
    int tid = threadIdx.x;

    const float* in = (side ? g_gg : g_xg) + b * CH * HW;
    const float* ws[3];
    const float* bs[3];
    int nset;
    if (side == 0) {
        ws[0] = xq_w; ws[1] = xk_w; ws[2] = xv_w;
        bs[0] = xq_b; bs[1] = xk_b; bs[2] = xv_b;
        nset = 3;
    } else {
        ws[0] = gq_w; ws[1] = gk_w; ws[2] = gk_w;
        bs[0] = gq_b; bs[1] = gk_b; bs[2] = gk_b;
        nset = 2;
    }

    for (int i = tid; i < 2048; i += 128) {
        int c = i >> 5, p4 = (i & 31) * 4;
        *(float4*)(si + c * 128 + p4) = *(const float4*)(in + c * HW + n0 + p4);
    }
    for (int s = 0; s < nset; s++) {
        for (int i = tid; i < 512; i += 128) {
            int c = i >> 3, o = i & 7;
            swt[s * 512 + c * 8 + o] = ws[s][(og * 8 + o) * 64 + c];
        }
        if (tid < 8) sb2[s * 8 + tid] = bs[s][og * 8 + tid];
    }
    __syncthreads();

    u64 acc[3][4];
    #pragma unroll
    for (int s = 0; s < 3; s++)
        #pragma unroll
        for (int k = 0; k < 4; k++)
            acc[s][k] = pk2(sb2[s * 8 + 2 * k], sb2[s * 8 + 2 * k + 1]);

    if (side == 0) {
        for (int c = 0; c < 64; c++) {
            float iv = si[c * 128 + tid];
            u64 ivp = pk2(iv, iv);
            #pragma unroll
            for (int s = 0; s < 3; s++) {
                ulonglong2 wa = *(const ulonglong2*)(swt + s * 512 + c * 8);
                ulonglong2 wb = *(const ulonglong2*)(swt + s * 512 + c * 8 + 4);
                acc[s][0] = ffma2(ivp, wa.x, acc[s][0]);
                acc[s][1] = ffma2(ivp, wa.y, acc[s][1]);
                acc[s][2] = ffma2(ivp, wb.x, acc[s][2]);
                acc[s][3] = ffma2(ivp, wb.y, acc[s][3]);
            }
        }
    } else {
        for (int c = 0; c < 64; c++) {
            float iv = si[c * 128 + tid];
            u64 ivp = pk2(iv, iv);
            #pragma unroll
            for (int s = 0; s < 2; s++) {
                ulonglong2 wa = *(const ulonglong2*)(swt + s * 512 + c * 8);
                ulonglong2 wb = *(const ulonglong2*)(swt + s * 512 + c * 8 + 4);
                acc[s][0] = ffma2(ivp, wa.x, acc[s][0]);
                acc[s][1] = ffma2(ivp, wa.y, acc[s][1]);
                acc[s][2] = ffma2(ivp, wb.x, acc[s][2]);
                acc[s][3] = ffma2(ivp, wb.y, acc[s][3]);
            }
        }
    }

    float* qdst = side ? g_gq : g_xq;
    __nv_bfloat16* KhD = g_bkh + (long)side * BATCH * CH * HW;
    __nv_bfloat16* KlD = g_bkl + (long)side * BATCH * CH * HW;
    #pragma unroll
    for (int k = 0; k < 4; k++) {
        int i0 = (b * CH + og * 8 + 2 * k) * HW + n0 + tid;
        float lo, hi;
        upk2(acc[0][k], lo, hi);
        qdst[i0] = lo; qdst[i0 + HW] = hi;
        upk2(acc[1][k], lo, hi);
        wrb(KhD, KlD, i0, lo); wrb(KhD, KlD, i0 + HW, hi);
        if (side == 0) {
            upk2(acc[2][k], lo, hi);
            wrb(g_bvh, g_bvl, i0, lo); wrb(g_bvh, g_bvl, i0 + HW, hi);
        }
    }
}

// ---------------- 4. flash attention: split-KV, swizzled 128B rows ----------------
// grid (128, B, 2): x = nt*2 + split. block 128 = 4 warps; CTA: 64 Q-rows x 32 KV tiles.
// dyn smem: 2 buffers x {Kh,Kl,Vh,Vl} each 64x64 bf16 (8192 B) = 65536 B.
// Tile layout: byte(r, chunk) = r*128 + ((chunk ^ (r&7))<<4), chunk = 16B (8 bf16).
__global__ void __launch_bounds__(128) kattn() {
    extern __shared__ __align__(16) uint8_t dyn[];

    const int tid = threadIdx.x;
    const int lane = tid & 31, wid = tid >> 5;
    const int tg = lane & 3, g = lane >> 2;
    const int b = blockIdx.y, kind = blockIdx.z;
    const int nt = blockIdx.x >> 1, sp = blockIdx.x & 1;
    const int n0 = nt * 64;
    const int kt0 = sp * 32;
    const float* Qp = (kind ? g_gq : g_xq) + b * CH * HW;
    const __nv_bfloat16* Kh = g_bkh + ((long)kind * BATCH + b) * CH * HW;
    const __nv_bfloat16* Kl = g_bkl + ((long)kind * BATCH + b) * CH * HW;
    const __nv_bfloat16* Vh = g_bvh + (long)b * CH * HW;
    const __nv_bfloat16* Vl = g_bvl + (long)b * CH * HW;

    const uint32_t sb = su32(dyn);

    // ---- stage Q (hi/lo) swizzled, load A-frags ----
    for (int idx = tid; idx < 4096; idx += 128) {
        int i = idx & 63, c = idx >> 6;
        float a = Qp[c * HW + n0 + i];
        __nv_bfloat16 h = __float2bfloat16_rn(a);
        uint32_t off = (uint32_t)(i * 128 + ((((c >> 3) ^ (i & 7))) << 4) + (c & 7) * 2);
        *(__nv_bfloat16*)(dyn + off) = h;
        *(__nv_bfloat16*)(dyn + 8192 + off) = __float2bfloat16_rn(a - __bfloat162float(h));
    }
    __syncthreads();

    const int rl = lane & 15, hi_half = lane >> 4, r7 = rl & 7;
    uint32_t qh[4][4], ql[4][4];
    #pragma unroll
    for (int kc = 0; kc < 4; kc++) {
        uint32_t off = (uint32_t)((16 * wid + rl) * 128 + (((kc * 2 + hi_half) ^ r7) << 4));
        ldsm4(qh[kc], sb + off);
        ldsm4(ql[kc], sb + 8192 + off);
    }
    __syncthreads();

    float oacc[8][4];
    #pragma unroll
    for (int cb = 0; cb < 8; cb++) {
        oacc[cb][0] = 0.f; oacc[cb][1] = 0.f; oacc[cb][2] = 0.f; oacc[cb][3] = 0.f;
    }
    float mrow0 = -1e30f, mrow1 = -1e30f, lrow0 = 0.f, lrow1 = 0.f;

    // V-frag lane geometry
    const int vrow = ((lane >> 4) << 3) + (lane & 7);
    const int vch = (lane >> 3) & 1;
    const int v7 = lane & 7;

    // prefetch tile kt0 into buf0
    {
        int m0 = kt0 * 64;
        #pragma unroll
        for (int u = 0; u < 4; u++) {
            int i = tid + u * 128;
            int row = i >> 3, ch = i & 7;
            uint32_t dst = sb + row * 128 + (((ch ^ (row & 7))) << 4);
            long go = (long)row * HW + m0 + ch * 8;
            cpa16(dst,          Kh + go);
            cpa16(dst + 8192,   Kl + go);
            cpa16(dst + 16384,  Vh + go);
            cpa16(dst + 24576,  Vl + go);
        }
        CPA_COMMIT();
    }

    for (int kt = 0; kt < 32; kt++) {
        const uint32_t bufc = sb + (uint32_t)(kt & 1) * 32768;

        if (kt < 31) {
            uint32_t bufn = sb + (uint32_t)((kt + 1) & 1) * 32768;
            int m0n = (kt0 + kt + 1) * 64;
            #pragma unroll
            for (int u = 0; u < 4; u++) {
                int i = tid + u * 128;
                int row = i >> 3, ch = i & 7;
                uint32_t dst = bufn + row * 128 + (((ch ^ (row & 7))) << 4);
                long go = (long)row * HW + m0n + ch * 8;
                cpa16(dst,          Kh + go);
                cpa16(dst + 8192,   Kl + go);
                cpa16(dst + 16384,  Vh + go);
                cpa16(dst + 24576,  Vl + go);
            }
            CPA_COMMIT();
            CPA_WAIT1();
        } else {
            CPA_WAIT0();
        }
        __syncthreads();

        // ---- S = Q K^T (3 bf16 passes) ----
        float sa[8][4];
        #pragma unroll
        for (int nb = 0; nb < 8; nb++) {
            sa[nb][0] = 0.f; sa[nb][1] = 0.f; sa[nb][2] = 0.f; sa[nb][3] = 0.f;
        }
        #pragma unroll
        for (int kc = 0; kc < 4; kc++) {
            #pragma unroll
            for (int jb = 0; jb < 4; jb++) {
                uint32_t bh[4], bl[4];
                uint32_t koff = (uint32_t)((kc * 16 + rl) * 128 +
                                           (((jb * 2 + hi_half) ^ r7) << 4));
                ldsm4t(bh, bufc + koff);
                ldsm4t(bl, bufc + 8192 + koff);
                mma_bf16(sa[2 * jb],     qh[kc], bh[0], bh[1]);
                mma_bf16(sa[2 * jb],     qh[kc], bl[0], bl[1]);
                mma_bf16(sa[2 * jb],     ql[kc], bh[0], bh[1]);
                mma_bf16(sa[2 * jb + 1], qh[kc], bh[2], bh[3]);
                mma_bf16(sa[2 * jb + 1], qh[kc], bl[2], bl[3]);
                mma_bf16(sa[2 * jb + 1], ql[kc], bh[2], bh[3]);
            }
        }

        // ---- online softmax ----
        float tm0 = -1e30f, tm1 = -1e30f;
        #pragma unroll
        for (int nb = 0; nb < 8; nb++) {
            tm0 = fmaxf(tm0, fmaxf(sa[nb][0], sa[nb][1]));
            tm1 = fmaxf(tm1, fmaxf(sa[nb][2], sa[nb][3]));
        }
        tm0 = fmaxf(tm0, __shfl_xor_sync(0xffffffffu, tm0, 1));
        tm0 = fmaxf(tm0, __shfl_xor_sync(0xffffffffu, tm0, 2));
        tm1 = fmaxf(tm1, __shfl_xor_sync(0xffffffffu, tm1, 1));
        tm1 = fmaxf(tm1, __shfl_xor_sync(0xffffffffu, tm1, 2));
        float mn0 = fmaxf(mrow0, tm0), mn1 = fmaxf(mrow1, tm1);
        float corr0 = __expf(mrow0 - mn0), corr1 = __expf(mrow1 - mn1);
        mrow0 = mn0; mrow1 = mn1;

        float ps0 = 0.f, ps1 = 0.f;
        #pragma unroll
        for (int nb = 0; nb < 8; nb++) {
            sa[nb][0] = __expf(sa[nb][0] - mn0);
            sa[nb][1] = __expf(sa[nb][1] - mn0);
            sa[nb][2] = __expf(sa[nb][2] - mn1);
            sa[nb][3] = __expf(sa[nb][3] - mn1);
            ps0 += sa[nb][0] + sa[nb][1];
            ps1 += sa[nb][2] + sa[nb][3];
        }
        ps0 += __shfl_xor_sync(0xffffffffu, ps0, 1);
        ps0 += __shfl_xor_sync(0xffffffffu, ps0, 2);
        ps1 += __shfl_xor_sync(0xffffffffu, ps1, 1);
        ps1 += __shfl_xor_sync(0xffffffffu, ps1, 2);
        lrow0 = lrow0 * corr0 + ps0;
        lrow1 = lrow1 * corr1 + ps1;

        #pragma unroll
        for (int cb = 0; cb < 8; cb++) {
            oacc[cb][0] *= corr0; oacc[cb][1] *= corr0;
            oacc[cb][2] *= corr1; oacc[cb][3] *= corr1;
        }

        // ---- P a-frags in registers (hi/lo) ----
        uint32_t ph[4][4], pl[4][4];
        #pragma unroll
        for (int kc = 0; kc < 4; kc++) {
            split2(sa[2 * kc][0],     sa[2 * kc][1],     ph[kc][0], pl[kc][0]);
            split2(sa[2 * kc][2],     sa[2 * kc][3],     ph[kc][1], pl[kc][1]);
            split2(sa[2 * kc + 1][0], sa[2 * kc + 1][1], ph[kc][2], pl[kc][2]);
            split2(sa[2 * kc + 1][2], sa[2 * kc + 1][3], ph[kc][3], pl[kc][3]);
        }

        // ---- O += P V^T (3 bf16 passes) ----
        #pragma unroll
        for (int kc = 0; kc < 4; kc++) {
            #pragma unroll
            for (int cp = 0; cp < 4; cp++) {
                uint32_t bh[4], bl[4];
                uint32_t voff = (uint32_t)((cp * 16 + vrow) * 128 +
                                           (((kc * 2 + vch) ^ v7) << 4));
                ldsm4(bh, bufc + 16384 + voff);
                ldsm4(bl, bufc + 24576 + voff);
                mma_bf16(oacc[2 * cp],     ph[kc], bh[0], bh[1]);
                mma_bf16(oacc[2 * cp],     ph[kc], bl[0], bl[1]);
                mma_bf16(oacc[2 * cp],     pl[kc], bh[0], bh[1]);
                mma_bf16(oacc[2 * cp + 1], ph[kc], bh[2], bh[3]);
                mma_bf16(oacc[2 * cp + 1], ph[kc], bl[2], bl[3]);
                mma_bf16(oacc[2 * cp + 1], pl[kc], bh[2], bh[3]);
            }
        }
        __syncthreads();
    }

    // ---- epilogue: store unnormalized partials + (m, l) ----
    long pbase = ((((long)kind * BATCH + b) * 2 + sp) * CH) * HW;
    int i0 = n0 + 16 * wid + g;
    #pragma unroll
    for (int cb = 0; cb < 8; cb++) {
        int c = 8 * cb + 2 * tg;
        g_pO[pbase + (long)c * HW + i0]           = oacc[cb][0];
        g_pO[pbase + (long)(c + 1) * HW + i0]     = oacc[cb][1];
        g_pO[pbase + (long)c * HW + i0 + 8]       = oacc[cb][2];
        g_pO[pbase + (long)(c + 1) * HW + i0 + 8] = oacc[cb][3];
    }
    if (tg == 0) {
        long mb = (((long)kind * 2 + b) * 2 + sp) * HW;
        g_pm[mb + i0] = mrow0;     g_pl[mb + i0] = lrow0;
        g_pm[mb + i0 + 8] = mrow1; g_pl[mb + i0 + 8] = lrow1;
    }
}

// ---------------- 4b. merge the two KV splits ----------------
__global__ void kmerge() {
    int t = blockIdx.x * 256 + threadIdx.x;   // 2*2*64*4096 elements
    int i = t & 4095;
    int c = (t >> 12) & 63;
    int b = (t >> 18) & 1;
    int kind = (t >> 19) & 1;
    long mb = (((long)kind * 2 + b) * 2) * HW;
    float m0 = g_pm[mb + i], m1 = g_pm[mb + HW + i];
    float l0 = g_pl[mb + i], l1 = g_pl[mb + HW + i];
    float m = fmaxf(m0, m1);
    float w0 = __expf(m0 - m), w1 = __expf(m1 - m);
    float inv = 1.f / (w0 * l0 + w1 * l1);
    long ob = ((((long)kind * 2 + b) * 2) * CH + c) * HW + i;
    float o = (w0 * g_pO[ob] + w1 * g_pO[ob + (long)CH * HW]) * inv;
    float* dst = kind ? g_gout : g_xout;
    dst[(b * CH + c) * HW + i] = o;
}

// ---------------- 5. combine ----------------
__global__ void kcombine(const float* __restrict__ gamma, const float* __restrict__ alpha) {
    int i = blockIdx.x * 256 + threadIdx.x;
    g_outb[i] = gamma[0] * g_xout[i] + alpha[0] * g_gout[i];
}

// ---------------- 6. plain conv3x3: 4 oc per block (R7 scalar form) ----------------
__global__ void __launch_bounds__(256) kconv3(const float* __restrict__ w,
                                              const float* __restrict__ bias,
                                              int in_id, int out_id, int leaky_in,
                                              int finalize, float* __restrict__ dout) {
    const float* inb = pick_in(in_id);
    int b = blockIdx.z, ocg = blockIdx.y;

    __shared__ float ws[4 * 576];
    for (int i = threadIdx.x; i < 4 * 576; i += 256) {
        int o = i / 576, r = i % 576;
        ws[o * 576 + r] = w[(ocg * 4 + o) * 576 + r];
    }
    __syncthreads();

    int p = blockIdx.x * 1024 + threadIdx.x * 4;
    int row = p >> 6, col0 = p & 63;
    float acc[4][4];
    #pragma unroll
    for (int o = 0; o < 4; o++) {
        float bv = bias[ocg * 4 + o];
        #pragma unroll
        for (int u = 0; u < 4; u++) acc[o][u] = bv;
    }
    const float* in = inb + b * CH * HW;

    for (int ic = 0; ic < 64; ic++) {
        const float* ch = in + ic * HW;
        #pragma unroll
        for (int kh = 0; kh < 3; kh++) {
            int hh = row + kh - 1;
            if ((unsigned)hh >= 64u) continue;
            float v[6];
            #pragma unroll
            for (int u = 0; u < 6; u++) {
                int cc = col0 - 1 + u;
                float val = ((unsigned)cc < 64u) ? ch[hh * 64 + cc] : 0.f;
                if (leaky_in) val = val > 0.f ? val : 0.1f * val;
                v[u] = val;
            }
            #pragma unroll
            for (int o = 0; o < 4; o++) {
                const float* wr = &ws[o * 576 + ic * 9 + kh * 3];
                #pragma unroll
                for (int kw = 0; kw < 3; kw++) {
                    float wv = wr[kw];
                    acc[o][0] += wv * v[kw + 0];
                    acc[o][1] += wv * v[kw + 1];
                    acc[o][2] += wv * v[kw + 2];
                    acc[o][3] += wv * v[kw + 3];
                }
            }
        }
    }
    if (finalize) {
        #pragma unroll
        for (int o = 0; o < 4; o++) {
            int base = (b * CH + ocg * 4 + o) * HW + p;
            float4 scv = *(const float4*)(g_sc + base);
            float4 gov = *(const float4*)(g_gout + base);
            *(float4*)(dout + base) = make_float4(acc[o][0] + scv.x * gov.x,
                                                  acc[o][1] + scv.y * gov.y,
                                                  acc[o][2] + scv.z * gov.z,
                                                  acc[o][3] + scv.w * gov.w);
        }
    } else {
        float* outb = pick_out(out_id);
        #pragma unroll
        for (int o = 0; o < 4; o++) {
            float* op = outb + (b * CH + ocg * 4 + o) * HW + p;
            *(float4*)op = make_float4(acc[o][0], acc[o][1], acc[o][2], acc[o][3]);
        }
    }
}

// ---------------- 3b. 1x1 conv (shortcut path) ----------------
__global__ void k1x1(const float* __restrict__ w, const float* __restrict__ bias,
                     int in_id, int out_id) {
    const float* in = pick_in(in_id);
    float* out = pick_out(out_id);
    int b = blockIdx.z, og = blockIdx.y;
    int n0 = blockIdx.x * 128;

    __shared__ float si[64 * 128];
    __shared__ float sw[8 * 64];
    for (int i = threadIdx.x; i < 64 * 128; i += 128) {
        int c = i >> 7, px = i & 127;
        si[i] = in[(b * CH + c) * HW + n0 + px];
    }
    for (int i = threadIdx.x; i < 512; i += 128)
        sw[i] = w[(og * 8 + (i >> 6)) * 64 + (i & 63)];
    __syncthreads();

    float acc[8];
    #pragma unroll
    for (int o = 0; o < 8; o++) acc[o] = bias[og * 8 + o];
    for (int c = 0; c < 64; c++) {
        float iv = si[c * 128 + threadIdx.x];
        #pragma unroll
        for (int o = 0; o < 8; o++) acc[o] += sw[o * 64 + c] * iv;
    }
    #pragma unroll
    for (int o = 0; o < 8; o++)
        out[(b * CH + og * 8 + o) * HW + n0 + threadIdx.x] = acc[o];
}

extern "C" void kernel_launch(void* const* d_in, const int* in_sizes, int n_in,
                              void* d_out, int out_size) {
    const float* x       = (const float*)d_in[0];
    const float* guide   = (const float*)d_in[1];
    const float* lin_w   = (const float*)d_in[2];
    const float* lin_b   = (const float*)d_in[3];
    const float* coord_w = (const float*)d_in[4];
    const float* xq_w = (const float*)d_in[5];
    const float* xq_b = (const float*)d_in[6];
    const float* xk_w = (const float*)d_in[7];
    const float* xk_b = (const float*)d_in[8];
    const float* xv_w = (const float*)d_in[9];
    const float* xv_b = (const float*)d_in[10];
    const float* gq_w = (const float*)d_in[11];
    const float* gq_b = (const float*)d_in[12];
    const float* gk_w = (const float*)d_in[13];
    const float* gk_b = (const float*)d_in[14];
    const float* gamma = (const float*)d_in[15];
    const float* alpha = (const float*)d_in[16];
    const float* c1_w = (const float*)d_in[17];
    const float* c1_b = (const float*)d_in[18];
    const float* c2_w = (const float*)d_in[19];
    const float* c2_b = (const float*)d_in[20];
    const float* sc_w = (const float*)d_in[21];
    const float* sc_b = (const float*)d_in[22];
    float* out = (float*)d_out;

    cudaFuncSetAttribute(kattn, cudaFuncAttributeMaxDynamicSharedMemorySize, 65536);

    kstats<<<256, 256>>>(x, guide, lin_w, lin_b);
    kgated<<<dim3(4, 16, 4), 256>>>(x, guide, coord_w);

    kproj<<<dim3(32, 8, 4), 128>>>(xq_w, xq_b, xk_w, xk_b, xv_w, xv_b,
                                   gq_w, gq_b, gk_w, gk_b);

    kattn<<<dim3(128, BATCH, 2), 128, 65536>>>();
    kmerge<<<8192, 256>>>();

    kcombine<<<2048, 256>>>(gamma, alpha);

    kconv3<<<dim3(4, 16, BATCH), 256>>>(c1_w, c1_b, BUF_OUT, BUF_OT1, 1, 0, nullptr);
    k1x1<<<dim3(32, 8, BATCH), 128>>>(sc_w, sc_b, BUF_OUT, BUF_SC);
    kconv3<<<dim3(4, 16, BATCH), 256>>>(c2_w, c2_b, BUF_T1, 0, 1, 1, out);
}

// round 10
// speedup vs baseline: 1.1304x; 1.0069x over previous
#include <cuda_runtime.h>
#include <cuda_bf16.h>
#include <cstdint>

#define BATCH 2
#define CH 64
#define HW 4096   // 64*64

typedef unsigned long long u64;

__device__ __forceinline__ u64 pk2(float lo, float hi) {
    u64 r; asm("mov.b64 %0,{%1,%2};" : "=l"(r) : "f"(lo), "f"(hi)); return r;
}
__device__ __forceinline__ void upk2(u64 v, float& lo, float& hi) {
    asm("mov.b64 {%0,%1},%2;" : "=f"(lo), "=f"(hi) : "l"(v));
}
__device__ __forceinline__ u64 ffma2(u64 a, u64 b, u64 c) {
    u64 d; asm("fma.rn.f32x2 %0,%1,%2,%3;" : "=l"(d) : "l"(a), "l"(b), "l"(c)); return d;
}

// ---------------- scratch ----------------
__device__ float g_scale[4 * CH];
__device__ float g_xg[BATCH * CH * HW];
__device__ float g_gg[BATCH * CH * HW];
__device__ float g_xq[BATCH * CH * HW];
__device__ float g_gq[BATCH * CH * HW];
__device__ float g_gout[BATCH * CH * HW];
__device__ float g_outb[BATCH * CH * HW];
__device__ float g_t1[BATCH * CH * HW];
__device__ float g_sc[BATCH * CH * HW];
__device__ __nv_bfloat16 g_bkh[2 * BATCH * CH * HW];
__device__ __nv_bfloat16 g_bkl[2 * BATCH * CH * HW];
__device__ __nv_bfloat16 g_bvh[BATCH * CH * HW];
__device__ __nv_bfloat16 g_bvl[BATCH * CH * HW];
// split-KV partials: O [kind][b][split][c][hw], m/l [kind][b][split][hw]
__device__ float g_pO[2 * BATCH * 2 * CH * HW];
__device__ float g_pm[2 * BATCH * 2 * HW];
__device__ float g_pl[2 * BATCH * 2 * HW];

#define BUF_XG 0
#define BUF_GG 1
#define BUF_OUT 2
#define BUF_T1 3

#define BUF_SC 5
#define BUF_OT1 6

__device__ __forceinline__ float* pick_in(int w) {
    switch (w) {
        case BUF_XG: return g_xg;
        case BUF_GG: return g_gg;
        case BUF_OUT: return g_outb;
        default:     return g_t1;
    }
}
__device__ __forceinline__ float* pick_out(int w) {
    switch (w) {
        case BUF_SC: return g_sc;
        default:     return g_t1;
    }
}

// ================= helpers =================
__device__ __forceinline__ uint32_t su32(const void* p) {
    uint32_t a;
    asm("{ .reg .u64 t; cvta.to.shared.u64 t, %1; cvt.u32.u64 %0, t; }" : "=r"(a) : "l"(p));
    return a;
}
__device__ __forceinline__ void mma_bf16(float* d, const uint32_t* a, uint32_t b0, uint32_t b1) {
    asm volatile(
        "mma.sync.aligned.m16n8k16.row.col.f32.bf16.bf16.f32 "
        "{%0,%1,%2,%3}, {%4,%5,%6,%7}, {%8,%9}, {%0,%1,%2,%3};"
        : "+f"(d[0]), "+f"(d[1]), "+f"(d[2]), "+f"(d[3])
        : "r"(a[0]), "r"(a[1]), "r"(a[2]), "r"(a[3]), "r"(b0), "r"(b1));
}
__device__ __forceinline__ void ldsm4(uint32_t* r, uint32_t addr) {
    asm volatile("ldmatrix.sync.aligned.m8n8.x4.shared.b16 {%0,%1,%2,%3}, [%4];"
                 : "=r"(r[0]), "=r"(r[1]), "=r"(r[2]), "=r"(r[3]) : "r"(addr));
}
__device__ __forceinline__ void ldsm4t(uint32_t* r, uint32_t addr) {
    asm volatile("ldmatrix.sync.aligned.m8n8.x4.trans.shared.b16 {%0,%1,%2,%3}, [%4];"
                 : "=r"(r[0]), "=r"(r[1]), "=r"(r[2]), "=r"(r[3]) : "r"(addr));
}
__device__ __forceinline__ uint32_t cvt_bf2(float lo, float hi) {
    uint32_t r;
    asm("cvt.rn.bf16x2.f32 %0, %1, %2;" : "=r"(r) : "f"(hi), "f"(lo));
    return r;
}
__device__ __forceinline__ void split2(float a, float b, uint32_t& hw, uint32_t& lw) {
    uint32_t h = cvt_bf2(a, b);
    float ra = a - __uint_as_float(h << 16);
    float rb = b - __uint_as_float(h & 0xFFFF0000u);
    hw = h;
    lw = cvt_bf2(ra, rb);
}
__device__ __forceinline__ void wrb(__nv_bfloat16* H, __nv_bfloat16* L, int idx, float v) {
    __nv_bfloat16 h = __float2bfloat16_rn(v);
    H[idx] = h;
    L[idx] = __float2bfloat16_rn(v - __bfloat162float(h));
}
__device__ __forceinline__ void cpa16(uint32_t dst, const void* src) {
    asm volatile("cp.async.cg.shared.global [%0], [%1], 16;" :: "r"(dst), "l"(src) : "memory");
}
#define CPA_COMMIT() asm volatile("cp.async.commit_group;" ::: "memory")
#define CPA_WAIT1()  asm volatile("cp.async.wait_group 1;" ::: "memory")
#define CPA_WAIT0()  asm volatile("cp.async.wait_group 0;" ::: "memory")

// ---------------- 1. channel attention scalars ----------------
__global__ void kstats(const float* __restrict__ x, const float* __restrict__ g,
                       const float* __restrict__ lw, const float* __restrict__ lb) {
    int idx = blockIdx.x;
    int t = idx >> 7, b = (idx >> 6) & 1, c = idx & 63;
    const float* in = (t ? g : x) + (b * CH + c) * HW;
    float s = 0.f;
    for (int i = threadIdx.x; i < HW; i += 256) s += in[i];
    __shared__ float red[8];
    #pragma unroll
    for (int o = 16; o > 0; o >>= 1) s += __shfl_xor_sync(0xffffffffu, s, o);
    if ((threadIdx.x & 31) == 0) red[threadIdx.x >> 5] = s;
    __syncthreads();
    if (threadIdx.x == 0) {
        float tot = 0.f;
        #pragma unroll
        for (int i = 0; i < 8; i++) tot += red[i];
        float p = tot * (1.0f / (float)HW);
        float W = lw[0], B = lb[0];
        float h = p * W + B;
        h = h > 0.f ? h : 0.1f * h;
        float z = h * W + B;
        g_scale[idx] = 1.f / (1.f + expf(-z));
    }
}

// ---------------- 2. gated coord conv: 4 oc per block ----------------
__global__ void __launch_bounds__(256) kgated(const float* __restrict__ xin,
                                              const float* __restrict__ gin,
                                              const float* __restrict__ cw) {
    int z = blockIdx.z;
    int t = z >> 1, b = z & 1;
    const float* in = (t ? gin : xin) + b * CH * HW;
    float* out = (t ? g_gg : g_xg) + b * CH * HW;
    int ocg = blockIdx.y;

    __shared__ float ws[4 * 66 * 9];
    for (int i = threadIdx.x; i < 4 * 594; i += 256) {
        int o = i / 594, r = i % 594;
        ws[o * 594 + r] = cw[(ocg * 4 + o) * 594 + r];
    }
    __syncthreads();

    int p = blockIdx.x * 1024 + threadIdx.x * 4;
    int row = p >> 6, col0 = p & 63;
    float acc[4][4];
    #pragma unroll
    for (int o = 0; o < 4; o++)
        #pragma unroll
        for (int u = 0; u < 4; u++) acc[o][u] = 0.f;

    for (int ic = 0; ic < 64; ic++) {
        const float* ch = in + ic * HW;
        #pragma unroll
        for (int kh = 0; kh < 3; kh++) {
            int hh = row + kh - 1;
            if ((unsigned)hh >= 64u) continue;
            float v[6];
            #pragma unroll
            for (int u = 0; u < 6; u++) {
                int cc = col0 - 1 + u;
                v[u] = ((unsigned)cc < 64u) ? ch[hh * 64 + cc] : 0.f;
            }
            #pragma unroll
            for (int o = 0; o < 4; o++) {
                const float* wr = &ws[o * 594 + ic * 9 + kh * 3];
                #pragma unroll
                for (int kw = 0; kw < 3; kw++) {
                    float wv = wr[kw];
                    acc[o][0] += wv * v[kw + 0];
                    acc[o][1] += wv * v[kw + 1];
                    acc[o][2] += wv * v[kw + 2];
                    acc[o][3] += wv * v[kw + 3];
                }
            }
        }
    }
    #pragma unroll
    for (int ic = 64; ic < 66; ic++) {
        #pragma unroll
        for (int kh = 0; kh < 3; kh++) {
            int hh = row + kh - 1;
            if ((unsigned)hh >= 64u) continue;
            float yyv = (float)hh * (2.f / 63.f) - 1.f;
            float v[6];
            #pragma unroll
            for (int u = 0; u < 6; u++) {
                int cc = col0 - 1 + u;
                float val = 0.f;
                if ((unsigned)cc < 64u)
                    val = (ic == 64) ? ((float)cc * (2.f / 63.f) - 1.f) : yyv;
                v[u] = val;
            }
            #pragma unroll
            for (int o = 0; o < 4; o++) {
                const float* wr = &ws[o * 594 + ic * 9 + kh * 3];
                #pragma unroll
                for (int kw = 0; kw < 3; kw++) {
                    float wv = wr[kw];
                    acc[o][0] += wv * v[kw + 0];
                    acc[o][1] += wv * v[kw + 1];
                    acc[o][2] += wv * v[kw + 2];
                    acc[o][3] += wv * v[kw + 3];
                }
            }
        }
    }

    #pragma unroll
    for (int o = 0; o < 4; o++) {
        int oc = ocg * 4 + o;
        float s = g_scale[z * CH + oc];
        float* op = out + oc * HW + p;
        *(float4*)op = make_float4(s * acc[o][0], s * acc[o][1], s * acc[o][2], s * acc[o][3]);
    }
}

// ---------------- 3. fused QKV projections; K/V written as bf16 hi/lo ----------------
__global__ void __launch_bounds__(128) kproj(
    const float* __restrict__ xq_w, const float* __restrict__ xq_b,
    const float* __restrict__ xk_w, const float* __restrict__ xk_b,
    const float* __restrict__ xv_w, const float* __restrict__ xv_b,
    const float* __restrict__ gq_w, const float* __restrict__ gq_b,
    const float* __restrict__ gk_w, const float* __restrict__ gk_b) {
    __shared__ float si[64 * 128];
    __shared__ float swt[3 * 512];
    __shared__ float sb2[3 * 8];

    int z = blockIdx.z;
    int side = z >> 1, b = z & 1;
    int og = blockIdx.y;
    int n0 = blockIdx.x * 128;
    int tid = threadIdx.x;

    const float* in = (side ? g_gg : g_xg) + b * CH * HW;
    const float* ws[3];
    const float* bs[3];
    int nset;
    if (side == 0) {
        ws[0] = xq_w; ws[1] = xk_w; ws[2] = xv_w;
        bs[0] = xq_b; bs[1] = xk_b; bs[2] = xv_b;
        nset = 3;
    } else {
        ws[0] = gq_w; ws[1] = gk_w; ws[2] = gk_w;
        bs[0] = gq_b; bs[1] = gk_b; bs[2] = gk_b;
        nset = 2;
    }

    for (int i = tid; i < 2048; i += 128) {
        int c = i >> 5, p4 = (i & 31) * 4;
        *(float4*)(si + c * 128 + p4) = *(const float4*)(in + c * HW + n0 + p4);
    }
    for (int s = 0; s < nset; s++) {
        for (int i = tid; i < 512; i += 128) {
            int c = i >> 3, o = i & 7;
            swt[s * 512 + c * 8 + o] = ws[s][(og * 8 + o) * 64 + c];
        }
        if (tid < 8) sb2[s * 8 + tid] = bs[s][og * 8 + tid];
    }
    __syncthreads();

    u64 acc[3][4];
    #pragma unroll
    for (int s = 0; s < 3; s++)
        #pragma unroll
        for (int k = 0; k < 4; k++)
            acc[s][k] = pk2(sb2[s * 8 + 2 * k], sb2[s * 8 + 2 * k + 1]);

    if (side == 0) {
        for (int c = 0; c < 64; c++) {
            float iv = si[c * 128 + tid];
            u64 ivp = pk2(iv, iv);
            #pragma unroll
            for (int s = 0; s < 3; s++) {
                ulonglong2 wa = *(const ulonglong2*)(swt + s * 512 + c * 8);
                ulonglong2 wb = *(const ulonglong2*)(swt + s * 512 + c * 8 + 4);
                acc[s][0] = ffma2(ivp, wa.x, acc[s][0]);
                acc[s][1] = ffma2(ivp, wa.y, acc[s][1]);
                acc[s][2] = ffma2(ivp, wb.x, acc[s][2]);
                acc[s][3] = ffma2(ivp, wb.y, acc[s][3]);
            }
        }
    } else {
        for (int c = 0; c < 64; c++) {
            float iv = si[c * 128 + tid];
            u64 ivp = pk2(iv, iv);
            #pragma unroll
            for (int s = 0; s < 2; s++) {
                ulonglong2 wa = *(const ulonglong2*)(swt + s * 512 + c * 8);
                ulonglong2 wb = *(const ulonglong2*)(swt + s * 512 + c * 8 + 4);
                acc[s][0] = ffma2(ivp, wa.x, acc[s][0]);
                acc[s][1] = ffma2(ivp, wa.y, acc[s][1]);
                acc[s][2] = ffma2(ivp, wb.x, acc[s][2]);
                acc[s][3] = ffma2(ivp, wb.y, acc[s][3]);
            }
        }
    }

    float* qdst = side ? g_gq : g_xq;
    __nv_bfloat16* KhD = g_bkh + (long)side * BATCH * CH * HW;
    __nv_bfloat16* KlD = g_bkl + (long)side * BATCH * CH * HW;
    #pragma unroll
    for (int k = 0; k < 4; k++) {
        int i0 = (b * CH + og * 8 + 2 * k) * HW + n0 + tid;
        float lo, hi;
        upk2(acc[0][k], lo, hi);
        qdst[i0] = lo; qdst[i0 + HW] = hi;
        upk2(acc[1][k], lo, hi);
        wrb(KhD, KlD, i0, lo); wrb(KhD, KlD, i0 + HW, hi);
        if (side == 0) {
            upk2(acc[2][k], lo, hi);
            wrb(g_bvh, g_bvl, i0, lo); wrb(g_bvh, g_bvl, i0 + HW, hi);
        }
    }
}

// ---------------- 4. flash attention: split-KV, 32-row tiles, 32KB smem ----------------
// grid (128, B, 2): x = nt*2 + split. block 128 = 4 warps; CTA: 64 Q-rows x 64 tiles of 32.
// dyn smem: 2 buffers x {Kh,Kl,Vh,Vl} each 64x32 bf16 (4096 B) = 32768 B.
// Tile layout: byte(r, ch) = r*64 + ((ch ^ ((r>>1)&3))<<4), ch = 16B chunk (0..3).
__global__ void __launch_bounds__(128, 4) kattn() {
    extern __shared__ __align__(16) uint8_t dyn[];

    const int tid = threadIdx.x;
    const int lane = tid & 31, wid = tid >> 5;
    const int tg = lane & 3, g = lane >> 2;
    const int b = blockIdx.y, kind = blockIdx.z;
    const int nt = blockIdx.x >> 1, sp = blockIdx.x & 1;
    const int n0 = nt * 64;
    const int kt0 = sp * 64;                 // 64 tiles of 32 per split
    const float* Qp = (kind ? g_gq : g_xq) + b * CH * HW;
    const __nv_bfloat16* Kh = g_bkh + ((long)kind * BATCH + b) * CH * HW;
    const __nv_bfloat16* Kl = g_bkl + ((long)kind * BATCH + b) * CH * HW;
    const __nv_bfloat16* Vh = g_bvh + (long)b * CH * HW;
    const __nv_bfloat16* Vl = g_bvl + (long)b * CH * HW;

    const uint32_t sb = su32(dyn);

    // ---- stage Q (hi/lo, 128B rows swizzled) into first 16KB, load A-frags ----
    for (int idx = tid; idx < 4096; idx += 128) {
        int i = idx & 63, c = idx >> 6;
        float a = Qp[c * HW + n0 + i];
        __nv_bfloat16 h = __float2bfloat16_rn(a);
        uint32_t off = (uint32_t)(i * 128 + ((((c >> 3) ^ (i & 7))) << 4) + (c & 7) * 2);
        *(__nv_bfloat16*)(dyn + off) = h;
        *(__nv_bfloat16*)(dyn + 8192 + off) = __float2bfloat16_rn(a - __bfloat162float(h));
    }
    __syncthreads();

    const int rl = lane & 15, hi_half = lane >> 4, r7 = rl & 7;
    uint32_t qh[4][4], ql[4][4];
    #pragma unroll
    for (int kc = 0; kc < 4; kc++) {
        uint32_t off = (uint32_t)((16 * wid + rl) * 128 + (((kc * 2 + hi_half) ^ r7) << 4));
        ldsm4(qh[kc], sb + off);
        ldsm4(ql[kc], sb + 8192 + off);
    }
    __syncthreads();

    float oacc[8][4];
    #pragma unroll
    for (int cb = 0; cb < 8; cb++) {
        oacc[cb][0] = 0.f; oacc[cb][1] = 0.f; oacc[cb][2] = 0.f; oacc[cb][3] = 0.f;
    }
    float mrow0 = -1e30f, mrow1 = -1e30f, lrow0 = 0.f, lrow1 = 0.f;

    const int rsw = (rl >> 1) & 3;
    const int vrow = ((lane >> 4) << 3) + (lane & 7);
    const int vch = (lane >> 3) & 1;
    const int vsw = (vrow >> 1) & 3;

    // prefetch tile kt0 into buf0
    {
        int m0 = kt0 * 32;
        #pragma unroll
        for (int u = 0; u < 2; u++) {
            int i = tid + u * 128;
            int row = i >> 2, ch = i & 3;
            uint32_t dst = sb + row * 64 + (((ch ^ ((row >> 1) & 3))) << 4);
            long go = (long)row * HW + m0 + ch * 8;
            cpa16(dst,          Kh + go);
            cpa16(dst + 4096,   Kl + go);
            cpa16(dst + 8192,   Vh + go);
            cpa16(dst + 12288,  Vl + go);
        }
        CPA_COMMIT();
    }

    for (int kt = 0; kt < 64; kt++) {
        const uint32_t bufc = sb + (uint32_t)(kt & 1) * 16384;

        if (kt < 63) {
            uint32_t bufn = sb + (uint32_t)((kt + 1) & 1) * 16384;
            int m0n = (kt0 + kt + 1) * 32;
            #pragma unroll
            for (int u = 0; u < 2; u++) {
                int i = tid + u * 128;
                int row = i >> 2, ch = i & 3;
                uint32_t dst = bufn + row * 64 + (((ch ^ ((row >> 1) & 3))) << 4);
                long go = (long)row * HW + m0n + ch * 8;
                cpa16(dst,          Kh + go);
                cpa16(dst + 4096,   Kl + go);
                cpa16(dst + 8192,   Vh + go);
                cpa16(dst + 12288,  Vl + go);
            }
            CPA_COMMIT();
            CPA_WAIT1();
        } else {
            CPA_WAIT0();
        }
        __syncthreads();

        // ---- S = Q K^T (3 bf16 passes), 16i x 32j per warp ----
        float sa[4][4];
        #pragma unroll
        for (int nb = 0; nb < 4; nb++) {
            sa[nb][0] = 0.f; sa[nb][1] = 0.f; sa[nb][2] = 0.f; sa[nb][3] = 0.f;
        }
        #pragma unroll
        for (int kc = 0; kc < 4; kc++) {
            #pragma unroll
            for (int jb = 0; jb < 2; jb++) {
                uint32_t bh[4], bl[4];
                uint32_t koff = (uint32_t)((kc * 16 + rl) * 64 +
                                           (((jb * 2 + hi_half) ^ rsw) << 4));
                ldsm4t(bh, bufc + koff);
                ldsm4t(bl, bufc + 4096 + koff);
                mma_bf16(sa[2 * jb],     qh[kc], bh[0], bh[1]);
                mma_bf16(sa[2 * jb],     qh[kc], bl[0], bl[1]);
                mma_bf16(sa[2 * jb],     ql[kc], bh[0], bh[1]);
                mma_bf16(sa[2 * jb + 1], qh[kc], bh[2], bh[3]);
                mma_bf16(sa[2 * jb + 1], qh[kc], bl[2], bl[3]);
                mma_bf16(sa[2 * jb + 1], ql[kc], bh[2], bh[3]);
            }
        }

        // ---- online softmax ----
        float tm0 = -1e30f, tm1 = -1e30f;
        #pragma unroll
        for (int nb = 0; nb < 4; nb++) {
            tm0 = fmaxf(tm0, fmaxf(sa[nb][0], sa[nb][1]));
            tm1 = fmaxf(tm1, fmaxf(sa[nb][2], sa[nb][3]));
        }
        tm0 = fmaxf(tm0, __shfl_xor_sync(0xffffffffu, tm0, 1));
        tm0 = fmaxf(tm0, __shfl_xor_sync(0xffffffffu, tm0, 2));
        tm1 = fmaxf(tm1, __shfl_xor_sync(0xffffffffu, tm1, 1));
        tm1 = fmaxf(tm1, __shfl_xor_sync(0xffffffffu, tm1, 2));
        float mn0 = fmaxf(mrow0, tm0), mn1 = fmaxf(mrow1, tm1);
        float corr0 = __expf(mrow0 - mn0), corr1 = __expf(mrow1 - mn1);
        mrow0 = mn0; mrow1 = mn1;

        float ps0 = 0.f, ps1 = 0.f;
        #pragma unroll
        for (int nb = 0; nb < 4; nb++) {
            sa[nb][0] = __expf(sa[nb][0] - mn0);
            sa[nb][1] = __expf(sa[nb][1] - mn0);
            sa[nb][2] = __expf(sa[nb][2] - mn1);
            sa[nb][3] = __expf(sa[nb][3] - mn1);
            ps0 += sa[nb][0] + sa[nb][1];
            ps1 += sa[nb][2] + sa[nb][3];
        }
        ps0 += __shfl_xor_sync(0xffffffffu, ps0, 1);
        ps0 += __shfl_xor_sync(0xffffffffu, ps0, 2);
        ps1 += __shfl_xor_sync(0xffffffffu, ps1, 1);
        ps1 += __shfl_xor_sync(0xffffffffu, ps1, 2);
        lrow0 = lrow0 * corr0 + ps0;
        lrow1 = lrow1 * corr1 + ps1;

        #pragma unroll
        for (int cb = 0; cb < 8; cb++) {
            oacc[cb][0] *= corr0; oacc[cb][1] *= corr0;
            oacc[cb][2] *= corr1; oacc[cb][3] *= corr1;
        }

        // ---- P a-frags in registers (hi/lo): 2 K-chunks of 16 j ----
        uint32_t ph[2][4], pl[2][4];
        #pragma unroll
        for (int kc = 0; kc < 2; kc++) {
            split2(sa[2 * kc][0],     sa[2 * kc][1],     ph[kc][0], pl[kc][0]);
            split2(sa[2 * kc][2],     sa[2 * kc][3],     ph[kc][1], pl[kc][1]);
            split2(sa[2 * kc + 1][0], sa[2 * kc + 1][1], ph[kc][2], pl[kc][2]);
            split2(sa[2 * kc + 1][2], sa[2 * kc + 1][3], ph[kc][3], pl[kc][3]);
        }

        // ---- O += P V^T (3 bf16 passes) ----
        #pragma unroll
        for (int kc = 0; kc < 2; kc++) {
            #pragma unroll
            for (int cp = 0; cp < 4; cp++) {
                uint32_t bh[4], bl[4];
                uint32_t voff = (uint32_t)((cp * 16 + vrow) * 64 +
                                           (((kc * 2 + vch) ^ vsw) << 4));
                ldsm4(bh, bufc + 8192 + voff);
                ldsm4(bl, bufc + 12288 + voff);
                mma_bf16(oacc[2 * cp],     ph[kc], bh[0], bh[1]);
                mma_bf16(oacc[2 * cp],     ph[kc], bl[0], bl[1]);
                mma_bf16(oacc[2 * cp],     pl[kc], bh[0], bh[1]);
                mma_bf16(oacc[2 * cp + 1], ph[kc], bh[2], bh[3]);
                mma_bf16(oacc[2 * cp + 1], ph[kc], bl[2], bl[3]);
                mma_bf16(oacc[2 * cp + 1], pl[kc], bh[2], bh[3]);
            }
        }
        __syncthreads();
    }

    // ---- epilogue: store unnormalized partials + (m, l) ----
    long pbase = ((((long)kind * BATCH + b) * 2 + sp) * CH) * HW;
    int i0 = n0 + 16 * wid + g;
    #pragma unroll
    for (int cb = 0; cb < 8; cb++) {
        int c = 8 * cb + 2 * tg;
        g_pO[pbase + (long)c * HW + i0]           = oacc[cb][0];
        g_pO[pbase + (long)(c + 1) * HW + i0]     = oacc[cb][1];
        g_pO[pbase + (long)c * HW + i0 + 8]       = oacc[cb][2];
        g_pO[pbase + (long)(c + 1) * HW + i0 + 8] = oacc[cb][3];
    }
    if (tg == 0) {
        long mb = (((long)kind * 2 + b) * 2 + sp) * HW;
        g_pm[mb + i0] = mrow0;     g_pl[mb + i0] = lrow0;
        g_pm[mb + i0 + 8] = mrow1; g_pl[mb + i0 + 8] = lrow1;
    }
}

// ---------------- 4b. merge splits + combine (gamma/alpha) fused ----------------
__global__ void kmergec(const float* __restrict__ gamma, const float* __restrict__ alpha) {
    int t = blockIdx.x * 256 + threadIdx.x;   // BATCH*CH*HW elements
    int i = t & 4095;
    int c = (t >> 12) & 63;
    int b = (t >> 18) & 1;
    float o[2];
    #pragma unroll
    for (int kind = 0; kind < 2; kind++) {
        long mb = (((long)kind * 2 + b) * 2) * HW;
        float m0 = g_pm[mb + i], m1 = g_pm[mb + HW + i];
        float l0 = g_pl[mb + i], l1 = g_pl[mb + HW + i];
        float m = fmaxf(m0, m1);
        float w0 = __expf(m0 - m), w1 = __expf(m1 - m);
        float inv = 1.f / (w0 * l0 + w1 * l1);
        long ob = ((((long)kind * BATCH + b) * 2) * CH + c) * HW + i;
        o[kind] = (w0 * g_pO[ob] + w1 * g_pO[ob + (long)CH * HW]) * inv;
    }
    int di = (b * CH + c) * HW + i;
    g_gout[di] = o[1];
    g_outb[di] = gamma[0] * o[0] + alpha[0] * o[1];
}

// ---------------- 6. plain conv3x3: 4 oc per block, optional fused final ----------------
__global__ void __launch_bounds__(256) kconv3(const float* __restrict__ w,
                                              const float* __restrict__ bias,
                                              int in_id, int out_id, int leaky_in,
                                              int finalize, float* __restrict__ dout) {
    const float* inb = pick_in(in_id);
    int b = blockIdx.z, ocg = blockIdx.y;

    __shared__ float ws[4 * 576];
    for (int i = threadIdx.x; i < 4 * 576; i += 256) {
        int o = i / 576, r = i % 576;
        ws[o * 576 + r] = w[(ocg * 4 + o) * 576 + r];
    }
    __syncthreads();

    int p = blockIdx.x * 1024 + threadIdx.x * 4;
    int row = p >> 6, col0 = p & 63;
    float acc[4][4];
    #pragma unroll
    for (int o = 0; o < 4; o++) {
        float bv = bias[ocg * 4 + o];
        #pragma unroll
        for (int u = 0; u < 4; u++) acc[o][u] = bv;
    }
    const float* in = inb + b * CH * HW;

    for (int ic = 0; ic < 64; ic++) {
        const float* ch = in + ic * HW;
        #pragma unroll
        for (int kh = 0; kh < 3; kh++) {
            int hh = row + kh - 1;
            if ((unsigned)hh >= 64u) continue;
            float v[6];
            #pragma unroll
            for (int u = 0; u < 6; u++) {
                int cc = col0 - 1 + u;
                float val = ((unsigned)cc < 64u) ? ch[hh * 64 + cc] : 0.f;
                if (leaky_in) val = val > 0.f ? val : 0.1f * val;
                v[u] = val;
            }
            #pragma unroll
            for (int o = 0; o < 4; o++) {
                const float* wr = &ws[o * 576 + ic * 9 + kh * 3];
                #pragma unroll
                for (int kw = 0; kw < 3; kw++) {
                    float wv = wr[kw];
                    acc[o][0] += wv * v[kw + 0];
                    acc[o][1] += wv * v[kw + 1];
                    acc[o][2] += wv * v[kw + 2];
                    acc[o][3] += wv * v[kw + 3];
                }
            }
        }
    }
    if (finalize) {
        #pragma unroll
        for (int o = 0; o < 4; o++) {
            int base = (b * CH + ocg * 4 + o) * HW + p;
            float4 scv = *(const float4*)(g_sc + base);
            float4 gov = *(const float4*)(g_gout + base);
            *(float4*)(dout + base) = make_float4(acc[o][0] + scv.x * gov.x,
                                                  acc[o][1] + scv.y * gov.y,
                                                  acc[o][2] + scv.z * gov.z,
                                                  acc[o][3] + scv.w * gov.w);
        }
    } else {
        float* outb = pick_out(out_id);
        #pragma unroll
        for (int o = 0; o < 4; o++) {
            float* op = outb + (b * CH + ocg * 4 + o) * HW + p;
            *(float4*)op = make_float4(acc[o][0], acc[o][1], acc[o][2], acc[o][3]);
        }
    }
}

// ---------------- 3b. 1x1 conv (shortcut path) ----------------
__global__ void k1x1(const float* __restrict__ w, const float* __restrict__ bias,
                     int in_id, int out_id) {
    const float* in = pick_in(in_id);
    float* out = pick_out(out_id);
    int b = blockIdx.z, og = blockIdx.y;
    int n0 = blockIdx.x * 128;

    __shared__ float si[64 * 128];
    __shared__ float sw[8 * 64];
    for (int i = threadIdx.x; i < 64 * 128; i += 128) {
        int c = i >> 7, px = i & 127;
        si[i] = in[(b * CH + c) * HW + n0 + px];
    }
    for (int i = threadIdx.x; i < 512; i += 128)
        sw[i] = w[(og * 8 + (i >> 6)) * 64 + (i & 63)];
    __syncthreads();

    float acc[8];
    #pragma unroll
    for (int o = 0; o < 8; o++) acc[o] = bias[og * 8 + o];
    for (int c = 0; c < 64; c++) {
        float iv = si[c * 128 + threadIdx.x];
        #pragma unroll
        for (int o = 0; o < 8; o++) acc[o] += sw[o * 64 + c] * iv;
    }
    #pragma unroll
    for (int o = 0; o < 8; o++)
        out[(b * CH + og * 8 + o) * HW + n0 + threadIdx.x] = acc[o];
}

extern "C" void kernel_launch(void* const* d_in, const int* in_sizes, int n_in,
                              void* d_out, int out_size) {
    const float* x       = (const float*)d_in[0];
    const float* guide   = (const float*)d_in[1];
    const float* lin_w   = (const float*)d_in[2];
    const float* lin_b   = (const float*)d_in[3];
    const float* coord_w = (const float*)d_in[4];
    const float* xq_w = (const float*)d_in[5];
    const float* xq_b = (const float*)d_in[6];
    const float* xk_w = (const float*)d_in[7];
    const float* xk_b = (const float*)d_in[8];
    const float* xv_w = (const float*)d_in[9];
    const float* xv_b = (const float*)d_in[10];
    const float* gq_w = (const float*)d_in[11];
    const float* gq_b = (const float*)d_in[12];
    const float* gk_w = (const float*)d_in[13];
    const float* gk_b = (const float*)d_in[14];
    const float* gamma = (const float*)d_in[15];
    const float* alpha = (const float*)d_in[16];
    const float* c1_w = (const float*)d_in[17];
    const float* c1_b = (const float*)d_in[18];
    const float* c2_w = (const float*)d_in[19];
    const float* c2_b = (const float*)d_in[20];
    const float* sc_w = (const float*)d_in[21];
    const float* sc_b = (const float*)d_in[22];
    float* out = (float*)d_out;

    cudaFuncSetAttribute(kattn, cudaFuncAttributeMaxDynamicSharedMemorySize, 32768);

    kstats<<<256, 256>>>(x, guide, lin_w, lin_b);
    kgated<<<dim3(4, 16, 4), 256>>>(x, guide, coord_w);

    kproj<<<dim3(32, 8, 4), 128>>>(xq_w, xq_b, xk_w, xk_b, xv_w, xv_b,
                                   gq_w, gq_b, gk_w, gk_b);

    kattn<<<dim3(128, BATCH, 2), 128, 32768>>>();
    kmergec<<<2048, 256>>>(gamma, alpha);

    kconv3<<<dim3(4, 16, BATCH), 256>>>(c1_w, c1_b, BUF_OUT, BUF_OT1, 1, 0, nullptr);
    k1x1<<<dim3(32, 8, BATCH), 128>>>(sc_w, sc_b, BUF_OUT, BUF_SC);
    kconv3<<<dim3(4, 16, BATCH), 256>>>(c2_w, c2_b, BUF_T1, 0, 1, 1, out);
}

// round 12
// speedup vs baseline: 1.1371x; 1.0059x over previous
#include <cuda_runtime.h>
#include <cuda_bf16.h>
#include <cstdint>

#define BATCH 2
#define CH 64
#define HW 4096   // 64*64
#define NSP 2     // KV splits

typedef unsigned long long u64;

__device__ __forceinline__ u64 pk2(float lo, float hi) {
    u64 r; asm("mov.b64 %0,{%1,%2};" : "=l"(r) : "f"(lo), "f"(hi)); return r;
}
__device__ __forceinline__ void upk2(u64 v, float& lo, float& hi) {
    asm("mov.b64 {%0,%1},%2;" : "=f"(lo), "=f"(hi) : "l"(v));
}
__device__ __forceinline__ u64 ffma2(u64 a, u64 b, u64 c) {
    u64 d; asm("fma.rn.f32x2 %0,%1,%2,%3;" : "=l"(d) : "l"(a), "l"(b), "l"(c)); return d;
}

// ---------------- scratch ----------------
__device__ float g_scale[4 * CH];
__device__ float g_xg[BATCH * CH * HW];
__device__ float g_gg[BATCH * CH * HW];
__device__ float g_xq[BATCH * CH * HW];
__device__ float g_gq[BATCH * CH * HW];
__device__ float g_gout[BATCH * CH * HW];
__device__ float g_outb[BATCH * CH * HW];
__device__ float g_t1[BATCH * CH * HW];
__device__ float g_sc[BATCH * CH * HW];
__device__ __nv_bfloat16 g_bkh[2 * BATCH * CH * HW];
__device__ __nv_bfloat16 g_bkl[2 * BATCH * CH * HW];
__device__ __nv_bfloat16 g_bvh[BATCH * CH * HW];
__device__ __nv_bfloat16 g_bvl[BATCH * CH * HW];
// split-KV partials: O [kind][b][split][c][hw], m/l [kind][b][split][hw]
__device__ float g_pO[2 * BATCH * NSP * CH * HW];
__device__ float g_pm[2 * BATCH * NSP * HW];
__device__ float g_pl[2 * BATCH * NSP * HW];

#define BUF_XG 0
#define BUF_GG 1
#define BUF_OUT 2
#define BUF_T1 3

#define BUF_SC 5
#define BUF_OT1 6

__device__ __forceinline__ float* pick_in(int w) {
    switch (w) {
        case BUF_XG: return g_xg;
        case BUF_GG: return g_gg;
        case BUF_OUT: return g_outb;
        default:     return g_t1;
    }
}
__device__ __forceinline__ float* pick_out(int w) {
    switch (w) {
        case BUF_SC: return g_sc;
        default:     return g_t1;
    }
}

// ================= helpers =================
__device__ __forceinline__ uint32_t su32(const void* p) {
    uint32_t a;
    asm("{ .reg .u64 t; cvta.to.shared.u64 t, %1; cvt.u32.u64 %0, t; }" : "=r"(a) : "l"(p));
    return a;
}
__device__ __forceinline__ void mma_bf16(float* d, const uint32_t* a, uint32_t b0, uint32_t b1) {
    asm volatile(
        "mma.sync.aligned.m16n8k16.row.col.f32.bf16.bf16.f32 "
        "{%0,%1,%2,%3}, {%4,%5,%6,%7}, {%8,%9}, {%0,%1,%2,%3};"
        : "+f"(d[0]), "+f"(d[1]), "+f"(d[2]), "+f"(d[3])
        : "r"(a[0]), "r"(a[1]), "r"(a[2]), "r"(a[3]), "r"(b0), "r"(b1));
}
__device__ __forceinline__ void ldsm4(uint32_t* r, uint32_t addr) {
    asm volatile("ldmatrix.sync.aligned.m8n8.x4.shared.b16 {%0,%1,%2,%3}, [%4];"
                 : "=r"(r[0]), "=r"(r[1]), "=r"(r[2]), "=r"(r[3]) : "r"(addr));
}
__device__ __forceinline__ void ldsm4t(uint32_t* r, uint32_t addr) {
    asm volatile("ldmatrix.sync.aligned.m8n8.x4.trans.shared.b16 {%0,%1,%2,%3}, [%4];"
                 : "=r"(r[0]), "=r"(r[1]), "=r"(r[2]), "=r"(r[3]) : "r"(addr));
}
__device__ __forceinline__ uint32_t cvt_bf2(float lo, float hi) {
    uint32_t r;
    asm("cvt.rn.bf16x2.f32 %0, %1, %2;" : "=r"(r) : "f"(hi), "f"(lo));
    return r;
}
__device__ __forceinline__ void split2(float a, float b, uint32_t& hw, uint32_t& lw) {
    uint32_t h = cvt_bf2(a, b);
    float ra = a - __uint_as_float(h << 16);
    float rb = b - __uint_as_float(h & 0xFFFF0000u);
    hw = h;
    lw = cvt_bf2(ra, rb);
}
__device__ __forceinline__ void wrb(__nv_bfloat16* H, __nv_bfloat16* L, int idx, float v) {
    __nv_bfloat16 h = __float2bfloat16_rn(v);
    H[idx] = h;
    L[idx] = __float2bfloat16_rn(v - __bfloat162float(h));
}
__device__ __forceinline__ void cpa16(uint32_t dst, const void* src) {
    asm volatile("cp.async.cg.shared.global [%0], [%1], 16;" :: "r"(dst), "l"(src) : "memory");
}
#define CPA_COMMIT() asm volatile("cp.async.commit_group;" ::: "memory")
#define CPA_WAIT0()  asm volatile("cp.async.wait_group 0;" ::: "memory")

// ---------------- 1. channel attention scalars ----------------
__global__ void kstats(const float* __restrict__ x, const float* __restrict__ g,
                       const float* __restrict__ lw, const float* __restrict__ lb) {
    int idx = blockIdx.x;
    int t = idx >> 7, b = (idx >> 6) & 1, c = idx & 63;
    const float* in = (t ? g : x) + (b * CH + c) * HW;
    float s = 0.f;
    for (int i = threadIdx.x; i < HW; i += 256) s += in[i];
    __shared__ float red[8];
    #pragma unroll
    for (int o = 16; o > 0; o >>= 1) s += __shfl_xor_sync(0xffffffffu, s, o);
    if ((threadIdx.x & 31) == 0) red[threadIdx.x >> 5] = s;
    __syncthreads();
    if (threadIdx.x == 0) {
        float tot = 0.f;
        #pragma unroll
        for (int i = 0; i < 8; i++) tot += red[i];
        float p = tot * (1.0f / (float)HW);
        float W = lw[0], B = lb[0];
        float h = p * W + B;
        h = h > 0.f ? h : 0.1f * h;
        float z = h * W + B;
        g_scale[idx] = 1.f / (1.f + expf(-z));
    }
}

// ---------------- 2. gated coord conv: 4 oc per block ----------------
__global__ void __launch_bounds__(256) kgated(const float* __restrict__ xin,
                                              const float* __restrict__ gin,
                                              const float* __restrict__ cw) {
    int z = blockIdx.z;
    int t = z >> 1, b = z & 1;
    const float* in = (t ? gin : xin) + b * CH * HW;
    float* out = (t ? g_gg : g_xg) + b * CH * HW;
    int ocg = blockIdx.y;

    __shared__ float ws[4 * 66 * 9];
    for (int i = threadIdx.x; i < 4 * 594; i += 256) {
        int o = i / 594, r = i % 594;
        ws[o * 594 + r] = cw[(ocg * 4 + o) * 594 + r];
    }
    __syncthreads();

    int p = blockIdx.x * 1024 + threadIdx.x * 4;
    int row = p >> 6, col0 = p & 63;
    float acc[4][4];
    #pragma unroll
    for (int o = 0; o < 4; o++)
        #pragma unroll
        for (int u = 0; u < 4; u++) acc[o][u] = 0.f;

    for (int ic = 0; ic < 64; ic++) {
        const float* ch = in + ic * HW;
        #pragma unroll
        for (int kh = 0; kh < 3; kh++) {
            int hh = row + kh - 1;
            if ((unsigned)hh >= 64u) continue;
            float v[6];
            #pragma unroll
            for (int u = 0; u < 6; u++) {
                int cc = col0 - 1 + u;
                v[u] = ((unsigned)cc < 64u) ? ch[hh * 64 + cc] : 0.f;
            }
            #pragma unroll
            for (int o = 0; o < 4; o++) {
                const float* wr = &ws[o * 594 + ic * 9 + kh * 3];
                #pragma unroll
                for (int kw = 0; kw < 3; kw++) {
                    float wv = wr[kw];
                    acc[o][0] += wv * v[kw + 0];
                    acc[o][1] += wv * v[kw + 1];
                    acc[o][2] += wv * v[kw + 2];
                    acc[o][3] += wv * v[kw + 3];
                }
            }
        }
    }
    #pragma unroll
    for (int ic = 64; ic < 66; ic++) {
        #pragma unroll
        for (int kh = 0; kh < 3; kh++) {
            int hh = row + kh - 1;
            if ((unsigned)hh >= 64u) continue;
            float yyv = (float)hh * (2.f / 63.f) - 1.f;
            float v[6];
            #pragma unroll
            for (int u = 0; u < 6; u++) {
                int cc = col0 - 1 + u;
                float val = 0.f;
                if ((unsigned)cc < 64u)
                    val = (ic == 64) ? ((float)cc * (2.f / 63.f) - 1.f) : yyv;
                v[u] = val;
            }
            #pragma unroll
            for (int o = 0; o < 4; o++) {
                const float* wr = &ws[o * 594 + ic * 9 + kh * 3];
                #pragma unroll
                for (int kw = 0; kw < 3; kw++) {
                    float wv = wr[kw];
                    acc[o][0] += wv * v[kw + 0];
                    acc[o][1] += wv * v[kw + 1];
                    acc[o][2] += wv * v[kw + 2];
                    acc[o][3] += wv * v[kw + 3];
                }
            }
        }
    }

    #pragma unroll
    for (int o = 0; o < 4; o++) {
        int oc = ocg * 4 + o;
        float s = g_scale[z * CH + oc];
        float* op = out + oc * HW + p;
        *(float4*)op = make_float4(s * acc[o][0], s * acc[o][1], s * acc[o][2], s * acc[o][3]);
    }
}

// ---------------- 3. fused QKV projections; K/V written as bf16 hi/lo ----------------
__global__ void __launch_bounds__(128) kproj(
    const float* __restrict__ xq_w, const float* __restrict__ xq_b,
    const float* __restrict__ xk_w, const float* __restrict__ xk_b,
    const float* __restrict__ xv_w, const float* __restrict__ xv_b,
    const float* __restrict__ gq_w, const float* __restrict__ gq_b,
    const float* __restrict__ gk_w, const float* __restrict__ gk_b) {
    __shared__ float si[64 * 128];
    __shared__ float swt[3 * 512];
    __shared__ float sb2[3 * 8];

    int z = blockIdx.z;
    int side = z >> 1, b = z & 1;
    int og = blockIdx.y;
    int n0 = blockIdx.x * 128;
    int tid = threadIdx.x;

    const float* in = (side ? g_gg : g_xg) + b * CH * HW;
    const float* ws[3];
    const float* bs[3];
    int nset;
    if (side == 0) {
        ws[0] = xq_w; ws[1] = xk_w; ws[2] = xv_w;
        bs[0] = xq_b; bs[1] = xk_b; bs[2] = xv_b;
        nset = 3;
    } else {
        ws[0] = gq_w; ws[1] = gk_w; ws[2] = gk_w;
        bs[0] = gq_b; bs[1] = gk_b; bs[2] = gk_b;
        nset = 2;
    }

    for (int i = tid; i < 2048; i += 128) {
        int c = i >> 5, p4 = (i & 31) * 4;
        *(float4*)(si + c * 128 + p4) = *(const float4*)(in + c * HW + n0 + p4);
    }
    for (int s = 0; s < nset; s++) {
        for (int i = tid; i < 512; i += 128) {
            int c = i >> 3, o = i & 7;
            swt[s * 512 + c * 8 + o] = ws[s][(og * 8 + o) * 64 + c];
        }
        if (tid < 8) sb2[s * 8 + tid] = bs[s][og * 8 + tid];
    }
    __syncthreads();

    u64 acc[3][4];
    #pragma unroll
    for (int s = 0; s < 3; s++)
        #pragma unroll
        for (int k = 0; k < 4; k++)
            acc[s][k] = pk2(sb2[s * 8 + 2 * k], sb2[s * 8 + 2 * k + 1]);

    if (side == 0) {
        for (int c = 0; c < 64; c++) {
            float iv = si[c * 128 + tid];
            u64 ivp = pk2(iv, iv);
            #pragma unroll
            for (int s = 0; s < 3; s++) {
                ulonglong2 wa = *(const ulonglong2*)(swt + s * 512 + c * 8);
                ulonglong2 wb = *(const ulonglong2*)(swt + s * 512 + c * 8 + 4);
                acc[s][0] = ffma2(ivp, wa.x, acc[s][0]);
                acc[s][1] = ffma2(ivp, wa.y, acc[s][1]);
                acc[s][2] = ffma2(ivp, wb.x, acc[s][2]);
                acc[s][3] = ffma2(ivp, wb.y, acc[s][3]);
            }
        }
    } else {
        for (int c = 0; c < 64; c++) {
            float iv = si[c * 128 + tid];
            u64 ivp = pk2(iv, iv);
            #pragma unroll
            for (int s = 0; s < 2; s++) {
                ulonglong2 wa = *(const ulonglong2*)(swt + s * 512 + c * 8);
                ulonglong2 wb = *(const ulonglong2*)(swt + s * 512 + c * 8 + 4);
                acc[s][0] = ffma2(ivp, wa.x, acc[s][0]);
                acc[s][1] = ffma2(ivp, wa.y, acc[s][1]);
                acc[s][2] = ffma2(ivp, wb.x, acc[s][2]);
                acc[s][3] = ffma2(ivp, wb.y, acc[s][3]);
            }
        }
    }

    float* qdst = side ? g_gq : g_xq;
    __nv_bfloat16* KhD = g_bkh + (long)side * BATCH * CH * HW;
    __nv_bfloat16* KlD = g_bkl + (long)side * BATCH * CH * HW;
    #pragma unroll
    for (int k = 0; k < 4; k++) {
        int i0 = (b * CH + og * 8 + 2 * k) * HW + n0 + tid;
        float lo, hi;
        upk2(acc[0][k], lo, hi);
        qdst[i0] = lo; qdst[i0 + HW] = hi;
        upk2(acc[1][k], lo, hi);
        wrb(KhD, KlD, i0, lo); wrb(KhD, KlD, i0 + HW, hi);
        if (side == 0) {
            upk2(acc[2][k], lo, hi);
            wrb(g_bvh, g_bvl, i0, lo); wrb(g_bvh, g_bvl, i0 + HW, hi);
        }
    }
}

// ---------------- 4. flash attention: split-KV, single 32KB buffer, 4 CTAs/SM ----------------
// grid (128, B, 2): x = nt*2 + split, nt=0..63. block 128 = 4 warps; CTA: 64 Q-rows x 32 tiles.
// dyn smem: ONE buffer {Kh,Kl,Vh,Vl} each 64x64 bf16 (8192 B) = 32768 B.
// Tile layout: byte(r, chunk) = r*128 + ((chunk ^ (r&7))<<4), chunk = 16B (8 bf16).
__global__ void __launch_bounds__(128, 4) kattn() {
    extern __shared__ __align__(16) uint8_t dyn[];

    const int tid = threadIdx.x;
    const int lane = tid & 31, wid = tid >> 5;
    const int tg = lane & 3, g = lane >> 2;
    const int b = blockIdx.y, kind = blockIdx.z;
    const int nt = blockIdx.x >> 1, sp = blockIdx.x & 1;
    const int n0 = nt * 64;
    const int kt0 = sp * 32;
    const float* Qp = (kind ? g_gq : g_xq) + b * CH * HW;
    const __nv_bfloat16* Kh = g_bkh + ((long)kind * BATCH + b) * CH * HW;
    const __nv_bfloat16* Kl = g_bkl + ((long)kind * BATCH + b) * CH * HW;
    const __nv_bfloat16* Vh = g_bvh + (long)b * CH * HW;
    const __nv_bfloat16* Vl = g_bvl + (long)b * CH * HW;

    const uint32_t sb = su32(dyn);

    // ---- stage Q (hi/lo) swizzled into the buffer, load A-frags ----
    for (int idx = tid; idx < 4096; idx += 128) {
        int i = idx & 63, c = idx >> 6;
        float a = Qp[c * HW + n0 + i];
        __nv_bfloat16 h = __float2bfloat16_rn(a);
        uint32_t off = (uint32_t)(i * 128 + ((((c >> 3) ^ (i & 7))) << 4) + (c & 7) * 2);
        *(__nv_bfloat16*)(dyn + off) = h;
        *(__nv_bfloat16*)(dyn + 8192 + off) = __float2bfloat16_rn(a - __bfloat162float(h));
    }
    __syncthreads();

    const int rl = lane & 15, hi_half = lane >> 4, r7 = rl & 7;
    uint32_t qh[4][4], ql[4][4];
    #pragma unroll
    for (int kc = 0; kc < 4; kc++) {
        uint32_t off = (uint32_t)((16 * wid + rl) * 128 + (((kc * 2 + hi_half) ^ r7) << 4));
        ldsm4(qh[kc], sb + off);
        ldsm4(ql[kc], sb + 8192 + off);
    }
    __syncthreads();

    float oacc[8][4];
    #pragma unroll
    for (int cb = 0; cb < 8; cb++) {
        oacc[cb][0] = 0.f; oacc[cb][1] = 0.f; oacc[cb][2] = 0.f; oacc[cb][3] = 0.f;
    }
    float mrow0 = -1e30f, mrow1 = -1e30f, lrow0 = 0.f, lrow1 = 0.f;

    const int vrow = ((lane >> 4) << 3) + (lane & 7);
    const int vch = (lane >> 3) & 1;
    const int v7 = lane & 7;

    for (int kt = 0; kt < 32; kt++) {
        // ---- load tile kt (single buffer) ----
        {
            int m0 = (kt0 + kt) * 64;
            #pragma unroll
            for (int u = 0; u < 4; u++) {
                int i = tid + u * 128;
                int row = i >> 3, ch = i & 7;
                uint32_t dst = sb + row * 128 + (((ch ^ (row & 7))) << 4);
                long go = (long)row * HW + m0 + ch * 8;
                cpa16(dst,          Kh + go);
                cpa16(dst + 8192,   Kl + go);
                cpa16(dst + 16384,  Vh + go);
                cpa16(dst + 24576,  Vl + go);
            }
            CPA_COMMIT();
            CPA_WAIT0();
        }
        __syncthreads();

        // ---- S = Q K^T (3 bf16 passes) ----
        float sa[8][4];
        #pragma unroll
        for (int nb = 0; nb < 8; nb++) {
            sa[nb][0] = 0.f; sa[nb][1] = 0.f; sa[nb][2] = 0.f; sa[nb][3] = 0.f;
        }
        #pragma unroll
        for (int kc = 0; kc < 4; kc++) {
            #pragma unroll
            for (int jb = 0; jb < 4; jb++) {
                uint32_t bh[4], bl[4];
                uint32_t koff = (uint32_t)((kc * 16 + rl) * 128 +
                                           (((jb * 2 + hi_half) ^ r7) << 4));
                ldsm4t(bh, sb + koff);
                ldsm4t(bl, sb + 8192 + koff);
                mma_bf16(sa[2 * jb],     qh[kc], bh[0], bh[1]);
                mma_bf16(sa[2 * jb],     qh[kc], bl[0], bl[1]);
                mma_bf16(sa[2 * jb],     ql[kc], bh[0], bh[1]);
                mma_bf16(sa[2 * jb + 1], qh[kc], bh[2], bh[3]);
                mma_bf16(sa[2 * jb + 1], qh[kc], bl[2], bl[3]);
                mma_bf16(sa[2 * jb + 1], ql[kc], bh[2], bh[3]);
            }
        }

        // ---- online softmax ----
        float tm0 = -1e30f, tm1 = -1e30f;
        #pragma unroll
        for (int nb = 0; nb < 8; nb++) {
            tm0 = fmaxf(tm0, fmaxf(sa[nb][0], sa[nb][1]));
            tm1 = fmaxf(tm1, fmaxf(sa[nb][2], sa[nb][3]));
        }
        tm0 = fmaxf(tm0, __shfl_xor_sync(0xffffffffu, tm0, 1));
        tm0 = fmaxf(tm0, __shfl_xor_sync(0xffffffffu, tm0, 2));
        tm1 = fmaxf(tm1, __shfl_xor_sync(0xffffffffu, tm1, 1));
        tm1 = fmaxf(tm1, __shfl_xor_sync(0xffffffffu, tm1, 2));
        float mn0 = fmaxf(mrow0, tm0), mn1 = fmaxf(mrow1, tm1);
        float corr0 = __expf(mrow0 - mn0), corr1 = __expf(mrow1 - mn1);
        mrow0 = mn0; mrow1 = mn1;

        float ps0 = 0.f, ps1 = 0.f;
        #pragma unroll
        for (int nb = 0; nb < 8; nb++) {
            sa[nb][0] = __expf(sa[nb][0] - mn0);
            sa[nb][1] = __expf(sa[nb][1] - mn0);
            sa[nb][2] = __expf(sa[nb][2] - mn1);
            sa[nb][3] = __expf(sa[nb][3] - mn1);
            ps0 += sa[nb][0] + sa[nb][1];
            ps1 += sa[nb][2] + sa[nb][3];
        }
        ps0 += __shfl_xor_sync(0xffffffffu, ps0, 1);
        ps0 += __shfl_xor_sync(0xffffffffu, ps0, 2);
        ps1 += __shfl_xor_sync(0xffffffffu, ps1, 1);
        ps1 += __shfl_xor_sync(0xffffffffu, ps1, 2);
        lrow0 = lrow0 * corr0 + ps0;
        lrow1 = lrow1 * corr1 + ps1;

        #pragma unroll
        for (int cb = 0; cb < 8; cb++) {
            oacc[cb][0] *= corr0; oacc[cb][1] *= corr0;
            oacc[cb][2] *= corr1; oacc[cb][3] *= corr1;
        }

        // ---- P a-frags in registers (hi/lo) ----
        uint32_t ph[4][4], pl[4][4];
        #pragma unroll
        for (int kc = 0; kc < 4; kc++) {
            split2(sa[2 * kc][0],     sa[2 * kc][1],     ph[kc][0], pl[kc][0]);
            split2(sa[2 * kc][2],     sa[2 * kc][3],     ph[kc][1], pl[kc][1]);
            split2(sa[2 * kc + 1][0], sa[2 * kc + 1][1], ph[kc][2], pl[kc][2]);
            split2(sa[2 * kc + 1][2], sa[2 * kc + 1][3], ph[kc][3], pl[kc][3]);
        }

        // ---- O += P V^T (3 bf16 passes) ----
        #pragma unroll
        for (int kc = 0; kc < 4; kc++) {
            #pragma unroll
            for (int cp = 0; cp < 4; cp++) {
                uint32_t bh[4], bl[4];
                uint32_t voff = (uint32_t)((cp * 16 + vrow) * 128 +
                                           (((kc * 2 + vch) ^ v7) << 4));
                ldsm4(bh, sb + 16384 + voff);
                ldsm4(bl, sb + 24576 + voff);
                mma_bf16(oacc[2 * cp],     ph[kc], bh[0], bh[1]);
                mma_bf16(oacc[2 * cp],     ph[kc], bl[0], bl[1]);
                mma_bf16(oacc[2 * cp],     pl[kc], bh[0], bh[1]);
                mma_bf16(oacc[2 * cp + 1], ph[kc], bh[2], bh[3]);
                mma_bf16(oacc[2 * cp + 1], ph[kc], bl[2], bl[3]);
                mma_bf16(oacc[2 * cp + 1], pl[kc], bh[2], bh[3]);
            }
        }
        __syncthreads();
    }

    // ---- epilogue: store unnormalized partials + (m, l) ----
    long pbase = ((((long)kind * BATCH + b) * NSP + sp) * CH) * HW;
    int i0 = n0 + 16 * wid + g;
    #pragma unroll
    for (int cb = 0; cb < 8; cb++) {
        int c = 8 * cb + 2 * tg;
        g_pO[pbase + (long)c * HW + i0]           = oacc[cb][0];
        g_pO[pbase + (long)(c + 1) * HW + i0]     = oacc[cb][1];
        g_pO[pbase + (long)c * HW + i0 + 8]       = oacc[cb][2];
        g_pO[pbase + (long)(c + 1) * HW + i0 + 8] = oacc[cb][3];
    }
    if (tg == 0) {
        long mb = (((long)kind * 2 + b) * NSP + sp) * HW;
        g_pm[mb + i0] = mrow0;     g_pl[mb + i0] = lrow0;
        g_pm[mb + i0 + 8] = mrow1; g_pl[mb + i0 + 8] = lrow1;
    }
}

// ---------------- 4b. merge 2 splits + combine (gamma/alpha) fused ----------------
__global__ void kmergec(const float* __restrict__ gamma, const float* __restrict__ alpha) {
    int t = blockIdx.x * 256 + threadIdx.x;   // BATCH*CH*HW elements
    int i = t & 4095;
    int c = (t >> 12) & 63;
    int b = (t >> 18) & 1;
    float o[2];
    #pragma unroll
    for (int kind = 0; kind < 2; kind++) {
        long mb = (((long)kind * 2 + b) * NSP) * HW;
        float m0 = g_pm[mb + i], m1 = g_pm[mb + HW + i];
        float l0 = g_pl[mb + i], l1 = g_pl[mb + HW + i];
        float m = fmaxf(m0, m1);
        float w0 = __expf(m0 - m), w1 = __expf(m1 - m);
        float inv = 1.f / (w0 * l0 + w1 * l1);
        long ob = ((((long)kind * BATCH + b) * NSP) * CH + c) * HW + i;
        o[kind] = (w0 * g_pO[ob] + w1 * g_pO[ob + (long)CH * HW]) * inv;
    }
    int di = (b * CH + c) * HW + i;
    g_gout[di] = o[1];
    g_outb[di] = gamma[0] * o[0] + alpha[0] * o[1];
}

// ---------------- 6. plain conv3x3: 4 oc per block, optional fused final ----------------
__global__ void __launch_bounds__(256) kconv3(const float* __restrict__ w,
                                              const float* __restrict__ bias,
                                              int in_id, int out_id, int leaky_in,
                                              int finalize, float* __restrict__ dout) {
    const float* inb = pick_in(in_id);
    int b = blockIdx.z, ocg = blockIdx.y;

    __shared__ float ws[4 * 576];
    for (int i = threadIdx.x; i < 4 * 576; i += 256) {
        int o = i / 576, r = i % 576;
        ws[o * 576 + r] = w[(ocg * 4 + o) * 576 + r];
    }
    __syncthreads();

    int p = blockIdx.x * 1024 + threadIdx.x * 4;
    int row = p >> 6, col0 = p & 63;
    float acc[4][4];
    #pragma unroll
    for (int o = 0; o < 4; o++) {
        float bv = bias[ocg * 4 + o];
        #pragma unroll
        for (int u = 0; u < 4; u++) acc[o][u] = bv;
    }
    const float* in = inb + b * CH * HW;

    for (int ic = 0; ic < 64; ic++) {
        const float* ch = in + ic * HW;
        #pragma unroll
        for (int kh = 0; kh < 3; kh++) {
            int hh = row + kh - 1;
            if ((unsigned)hh >= 64u) continue;
            float v[6];
            #pragma unroll
            for (int u = 0; u < 6; u++) {
                int cc = col0 - 1 + u;
                float val = ((unsigned)cc < 64u) ? ch[hh * 64 + cc] : 0.f;
                if (leaky_in) val = val > 0.f ? val : 0.1f * val;
                v[u] = val;
            }
            #pragma unroll
            for (int o = 0; o < 4; o++) {
                const float* wr = &ws[o * 576 + ic * 9 + kh * 3];
                #pragma unroll
                for (int kw = 0; kw < 3; kw++) {
                    float wv = wr[kw];
                    acc[o][0] += wv * v[kw + 0];
                    acc[o][1] += wv * v[kw + 1];
                    acc[o][2] += wv * v[kw + 2];
                    acc[o][3] += wv * v[kw + 3];
                }
            }
        }
    }
    if (finalize) {
        #pragma unroll
        for (int o = 0; o < 4; o++) {
            int base = (b * CH + ocg * 4 + o) * HW + p;
            float4 scv = *(const float4*)(g_sc + base);
            float4 gov = *(const float4*)(g_gout + base);
            *(float4*)(dout + base) = make_float4(acc[o][0] + scv.x * gov.x,
                                                  acc[o][1] + scv.y * gov.y,
                                                  acc[o][2] + scv.z * gov.z,
                                                  acc[o][3] + scv.w * gov.w);
        }
    } else {
        float* outb = pick_out(out_id);
        #pragma unroll
        for (int o = 0; o < 4; o++) {
            float* op = outb + (b * CH + ocg * 4 + o) * HW + p;
            *(float4*)op = make_float4(acc[o][0], acc[o][1], acc[o][2], acc[o][3]);
        }
    }
}

// ---------------- 3b. 1x1 conv (shortcut path) ----------------
__global__ void k1x1(const float* __restrict__ w, const float* __restrict__ bias,
                     int in_id, int out_id) {
    const float* in = pick_in(in_id);
    float* out = pick_out(out_id);
    int b = blockIdx.z, og = blockIdx.y;
    int n0 = blockIdx.x * 128;

    __shared__ float si[64 * 128];
    __shared__ float sw[8 * 64];
    for (int i = threadIdx.x; i < 64 * 128; i += 128) {
        int c = i >> 7, px = i & 127;
        si[i] = in[(b * CH + c) * HW + n0 + px];
    }
    for (int i = threadIdx.x; i < 512; i += 128)
        sw[i] = w[(og * 8 + (i >> 6)) * 64 + (i & 63)];
    __syncthreads();

    float acc[8];
    #pragma unroll
    for (int o = 0; o < 8; o++) acc[o] = bias[og * 8 + o];
    for (int c = 0; c < 64; c++) {
        float iv = si[c * 128 + threadIdx.x];
        #pragma unroll
        for (int o = 0; o < 8; o++) acc[o] += sw[o * 64 + c] * iv;
    }
    #pragma unroll
    for (int o = 0; o < 8; o++)
        out[(b * CH + og * 8 + o) * HW + n0 + threadIdx.x] = acc[o];
}

extern "C" void kernel_launch(void* const* d_in, const int* in_sizes, int n_in,
                              void* d_out, int out_size) {
    const float* x       = (const float*)d_in[0];
    const float* guide   = (const float*)d_in[1];
    const float* lin_w   = (const float*)d_in[2];
    const float* lin_b   = (const float*)d_in[3];
    const float* coord_w = (const float*)d_in[4];
    const float* xq_w = (const float*)d_in[5];
    const float* xq_b = (const float*)d_in[6];
    const float* xk_w = (const float*)d_in[7];
    const float* xk_b = (const float*)d_in[8];
    const float* xv_w = (const float*)d_in[9];
    const float* xv_b = (const float*)d_in[10];
    const float* gq_w = (const float*)d_in[11];
    const float* gq_b = (const float*)d_in[12];
    const float* gk_w = (const float*)d_in[13];
    const float* gk_b = (const float*)d_in[14];
    const float* gamma = (const float*)d_in[15];
    const float* alpha = (const float*)d_in[16];
    const float* c1_w = (const float*)d_in[17];
    const float* c1_b = (const float*)d_in[18];
    const float* c2_w = (const float*)d_in[19];
    const float* c2_b = (const float*)d_in[20];
    const float* sc_w = (const float*)d_in[21];
    const float* sc_b = (const float*)d_in[22];
    float* out = (float*)d_out;

    cudaFuncSetAttribute(kattn, cudaFuncAttributeMaxDynamicSharedMemorySize, 32768);

    kstats<<<256, 256>>>(x, guide, lin_w, lin_b);
    kgated<<<dim3(4, 16, 4), 256>>>(x, guide, coord_w);

    kproj<<<dim3(32, 8, 4), 128>>>(xq_w, xq_b, xk_w, xk_b, xv_w, xv_b,
                                   gq_w, gq_b, gk_w, gk_b);

    kattn<<<dim3(64 * NSP, BATCH, 2), 128, 32768>>>();
    kmergec<<<2048, 256>>>(gamma, alpha);

    kconv3<<<dim3(4, 16, BATCH), 256>>>(c1_w, c1_b, BUF_OUT, BUF_OT1, 1, 0, nullptr);
    k1x1<<<dim3(32, 8, BATCH), 128>>>(sc_w, sc_b, BUF_OUT, BUF_SC);
    kconv3<<<dim3(4, 16, BATCH), 256>>>(c2_w, c2_b, BUF_T1, 0, 1, 1, out);
}

// round 13
// speedup vs baseline: 1.1442x; 1.0062x over previous
#include <cuda_runtime.h>
#include <cuda_bf16.h>
#include <cstdint>

#define BATCH 2
#define CH 64
#define HW 4096   // 64*64
#define NSP 2     // KV splits

typedef unsigned long long u64;

__device__ __forceinline__ u64 pk2(float lo, float hi) {
    u64 r; asm("mov.b64 %0,{%1,%2};" : "=l"(r) : "f"(lo), "f"(hi)); return r;
}
__device__ __forceinline__ void upk2(u64 v, float& lo, float& hi) {
    asm("mov.b64 {%0,%1},%2;" : "=f"(lo), "=f"(hi) : "l"(v));
}
__device__ __forceinline__ u64 ffma2(u64 a, u64 b, u64 c) {
    u64 d; asm("fma.rn.f32x2 %0,%1,%2,%3;" : "=l"(d) : "l"(a), "l"(b), "l"(c)); return d;
}

// ---------------- scratch ----------------
__device__ float g_scale[4 * CH];
__device__ float g_xg[BATCH * CH * HW];
__device__ float g_gg[BATCH * CH * HW];
__device__ float g_xq[BATCH * CH * HW];
__device__ float g_gq[BATCH * CH * HW];
__device__ float g_gout[BATCH * CH * HW];
__device__ float g_outb[BATCH * CH * HW];
__device__ float g_t1[BATCH * CH * HW];
__device__ float g_sc[BATCH * CH * HW];
__device__ __nv_bfloat16 g_bkh[2 * BATCH * CH * HW];
__device__ __nv_bfloat16 g_bkl[2 * BATCH * CH * HW];
__device__ __nv_bfloat16 g_bvh[BATCH * CH * HW];
__device__ __nv_bfloat16 g_bvl[BATCH * CH * HW];
// split-KV partials
__device__ float g_pO[2 * BATCH * NSP * CH * HW];
__device__ float g_pm[2 * BATCH * NSP * HW];
__device__ float g_pl[2 * BATCH * NSP * HW];

#define BUF_XG 0
#define BUF_GG 1
#define BUF_OUT 2
#define BUF_T1 3

#define BUF_SC 5
#define BUF_OT1 6

__device__ __forceinline__ float* pick_in(int w) {
    switch (w) {
        case BUF_XG: return g_xg;
        case BUF_GG: return g_gg;
        case BUF_OUT: return g_outb;
        default:     return g_t1;
    }
}
__device__ __forceinline__ float* pick_out(int w) {
    switch (w) {
        case BUF_SC: return g_sc;
        default:     return g_t1;
    }
}

// ================= helpers =================
__device__ __forceinline__ uint32_t su32(const void* p) {
    uint32_t a;
    asm("{ .reg .u64 t; cvta.to.shared.u64 t, %1; cvt.u32.u64 %0, t; }" : "=r"(a) : "l"(p));
    return a;
}
__device__ __forceinline__ void mma_bf16(float* d, const uint32_t* a, uint32_t b0, uint32_t b1) {
    asm volatile(
        "mma.sync.aligned.m16n8k16.row.col.f32.bf16.bf16.f32 "
        "{%0,%1,%2,%3}, {%4,%5,%6,%7}, {%8,%9}, {%0,%1,%2,%3};"
        : "+f"(d[0]), "+f"(d[1]), "+f"(d[2]), "+f"(d[3])
        : "r"(a[0]), "r"(a[1]), "r"(a[2]), "r"(a[3]), "r"(b0), "r"(b1));
}
__device__ __forceinline__ void ldsm4(uint32_t* r, uint32_t addr) {
    asm volatile("ldmatrix.sync.aligned.m8n8.x4.shared.b16 {%0,%1,%2,%3}, [%4];"
                 : "=r"(r[0]), "=r"(r[1]), "=r"(r[2]), "=r"(r[3]) : "r"(addr));
}
__device__ __forceinline__ void ldsm4t(uint32_t* r, uint32_t addr) {
    asm volatile("ldmatrix.sync.aligned.m8n8.x4.trans.shared.b16 {%0,%1,%2,%3}, [%4];"
                 : "=r"(r[0]), "=r"(r[1]), "=r"(r[2]), "=r"(r[3]) : "r"(addr));
}
__device__ __forceinline__ uint32_t cvt_bf2(float lo, float hi) {
    uint32_t r;
    asm("cvt.rn.bf16x2.f32 %0, %1, %2;" : "=r"(r) : "f"(hi), "f"(lo));
    return r;
}
__device__ __forceinline__ void split2(float a, float b, uint32_t& hw, uint32_t& lw) {
    uint32_t h = cvt_bf2(a, b);
    float ra = a - __uint_as_float(h << 16);
    float rb = b - __uint_as_float(h & 0xFFFF0000u);
    hw = h;
    lw = cvt_bf2(ra, rb);
}
__device__ __forceinline__ void wrb(__nv_bfloat16* H, __nv_bfloat16* L, int idx, float v) {
    __nv_bfloat16 h = __float2bfloat16_rn(v);
    H[idx] = h;
    L[idx] = __float2bfloat16_rn(v - __bfloat162float(h));
}
__device__ __forceinline__ void cpa16(uint32_t dst, const void* src) {
    asm volatile("cp.async.cg.shared.global [%0], [%1], 16;" :: "r"(dst), "l"(src) : "memory");
}
#define CPA_COMMIT() asm volatile("cp.async.commit_group;" ::: "memory")
#define CPA_WAIT1()  asm volatile("cp.async.wait_group 1;" ::: "memory")
#define CPA_WAIT0()  asm volatile("cp.async.wait_group 0;" ::: "memory")

// ---------------- 1. channel attention scalars ----------------
__global__ void kstats(const float* __restrict__ x, const float* __restrict__ g,
                       const float* __restrict__ lw, const float* __restrict__ lb) {
    int idx = blockIdx.x;
    int t = idx >> 7, b = (idx >> 6) & 1, c = idx & 63;
    const float* in = (t ? g : x) + (b * CH + c) * HW;
    float s = 0.f;
    for (int i = threadIdx.x; i < HW; i += 256) s += in[i];
    __shared__ float red[8];
    #pragma unroll
    for (int o = 16; o > 0; o >>= 1) s += __shfl_xor_sync(0xffffffffu, s, o);
    if ((threadIdx.x & 31) == 0) red[threadIdx.x >> 5] = s;
    __syncthreads();
    if (threadIdx.x == 0) {
        float tot = 0.f;
        #pragma unroll
        for (int i = 0; i < 8; i++) tot += red[i];
        float p = tot * (1.0f / (float)HW);
        float W = lw[0], B = lb[0];
        float h = p * W + B;
        h = h > 0.f ? h : 0.1f * h;
        float z = h * W + B;
        g_scale[idx] = 1.f / (1.f + expf(-z));
    }
}

// ---------------- 2. gated coord conv: 4 oc, 2 px/thread, 512 CTAs ----------------
__global__ void __launch_bounds__(256) kgated(const float* __restrict__ xin,
                                              const float* __restrict__ gin,
                                              const float* __restrict__ cw) {
    int z = blockIdx.z;
    int t = z >> 1, b = z & 1;
    const float* in = (t ? gin : xin) + b * CH * HW;
    float* out = (t ? g_gg : g_xg) + b * CH * HW;
    int ocg = blockIdx.y;

    __shared__ float ws[4 * 66 * 9];
    for (int i = threadIdx.x; i < 4 * 594; i += 256) {
        int o = i / 594, r = i % 594;
        ws[o * 594 + r] = cw[(ocg * 4 + o) * 594 + r];
    }
    __syncthreads();

    int p = blockIdx.x * 512 + threadIdx.x * 2;
    int row = p >> 6, col0 = p & 63;
    float acc[4][2];
    #pragma unroll
    for (int o = 0; o < 4; o++) { acc[o][0] = 0.f; acc[o][1] = 0.f; }

    for (int ic = 0; ic < 64; ic++) {
        const float* ch = in + ic * HW;
        #pragma unroll
        for (int kh = 0; kh < 3; kh++) {
            int hh = row + kh - 1;
            if ((unsigned)hh >= 64u) continue;
            float v[4];
            #pragma unroll
            for (int u = 0; u < 4; u++) {
                int cc = col0 - 1 + u;
                v[u] = ((unsigned)cc < 64u) ? ch[hh * 64 + cc] : 0.f;
            }
            #pragma unroll
            for (int o = 0; o < 4; o++) {
                const float* wr = &ws[o * 594 + ic * 9 + kh * 3];
                #pragma unroll
                for (int kw = 0; kw < 3; kw++) {
                    float wv = wr[kw];
                    acc[o][0] += wv * v[kw + 0];
                    acc[o][1] += wv * v[kw + 1];
                }
            }
        }
    }
    #pragma unroll
    for (int ic = 64; ic < 66; ic++) {
        #pragma unroll
        for (int kh = 0; kh < 3; kh++) {
            int hh = row + kh - 1;
            if ((unsigned)hh >= 64u) continue;
            float yyv = (float)hh * (2.f / 63.f) - 1.f;
            float v[4];
            #pragma unroll
            for (int u = 0; u < 4; u++) {
                int cc = col0 - 1 + u;
                float val = 0.f;
                if ((unsigned)cc < 64u)
                    val = (ic == 64) ? ((float)cc * (2.f / 63.f) - 1.f) : yyv;
                v[u] = val;
            }
            #pragma unroll
            for (int o = 0; o < 4; o++) {
                const float* wr = &ws[o * 594 + ic * 9 + kh * 3];
                #pragma unroll
                for (int kw = 0; kw < 3; kw++) {
                    float wv = wr[kw];
                    acc[o][0] += wv * v[kw + 0];
                    acc[o][1] += wv * v[kw + 1];
                }
            }
        }
    }

    #pragma unroll
    for (int o = 0; o < 4; o++) {
        int oc = ocg * 4 + o;
        float s = g_scale[z * CH + oc];
        *(float2*)(out + oc * HW + p) = make_float2(s * acc[o][0], s * acc[o][1]);
    }
}

// ---------------- 3. fused QKV projections; K/V written as bf16 hi/lo ----------------
__global__ void __launch_bounds__(128) kproj(
    const float* __restrict__ xq_w, const float* __restrict__ xq_b,
    const float* __restrict__ xk_w, const float* __restrict__ xk_b,
    const float* __restrict__ xv_w, const float* __restrict__ xv_b,
    const float* __restrict__ gq_w, const float* __restrict__ gq_b,
    const float* __restrict__ gk_w, const float* __restrict__ gk_b) {
    __shared__ float si[64 * 128];
    __shared__ float swt[3 * 512];
    __shared__ float sb2[3 * 8];

    int z = blockIdx.z;
    int side = z >> 1, b = z & 1;
    int og = blockIdx.y;
    int n0 = blockIdx.x * 128;
    int tid = threadIdx.x;

    const float* in = (side ? g_gg : g_xg) + b * CH * HW;
    const float* ws[3];
    const float* bs[3];
    int nset;
    if (side == 0) {
        ws[0] = xq_w; ws[1] = xk_w; ws[2] = xv_w;
        bs[0] = xq_b; bs[1] = xk_b; bs[2] = xv_b;
        nset = 3;
    } else {
        ws[0] = gq_w; ws[1] = gk_w; ws[2] = gk_w;
        bs[0] = gq_b; bs[1] = gk_b; bs[2] = gk_b;
        nset = 2;
    }

    for (int i = tid; i < 2048; i += 128) {
        int c = i >> 5, p4 = (i & 31) * 4;
        *(float4*)(si + c * 128 + p4) = *(const float4*)(in + c * HW + n0 + p4);
    }
    for (int s = 0; s < nset; s++) {
        for (int i = tid; i < 512; i += 128) {
            int c = i >> 3, o = i & 7;
            swt[s * 512 + c * 8 + o] = ws[s][(og * 8 + o) * 64 + c];
        }
        if (tid < 8) sb2[s * 8 + tid] = bs[s][og * 8 + tid];
    }
    __syncthreads();

    u64 acc[3][4];
    #pragma unroll
    for (int s = 0; s < 3; s++)
        #pragma unroll
        for (int k = 0; k < 4; k++)
            acc[s][k] = pk2(sb2[s * 8 + 2 * k], sb2[s * 8 + 2 * k + 1]);

    if (side == 0) {
        for (int c = 0; c < 64; c++) {
            float iv = si[c * 128 + tid];
            u64 ivp = pk2(iv, iv);
            #pragma unroll
            for (int s = 0; s < 3; s++) {
                ulonglong2 wa = *(const ulonglong2*)(swt + s * 512 + c * 8);
                ulonglong2 wb = *(const ulonglong2*)(swt + s * 512 + c * 8 + 4);
                acc[s][0] = ffma2(ivp, wa.x, acc[s][0]);
                acc[s][1] = ffma2(ivp, wa.y, acc[s][1]);
                acc[s][2] = ffma2(ivp, wb.x, acc[s][2]);
                acc[s][3] = ffma2(ivp, wb.y, acc[s][3]);
            }
        }
    } else {
        for (int c = 0; c < 64; c++) {
            float iv = si[c * 128 + tid];
            u64 ivp = pk2(iv, iv);
            #pragma unroll
            for (int s = 0; s < 2; s++) {
                ulonglong2 wa = *(const ulonglong2*)(swt + s * 512 + c * 8);
                ulonglong2 wb = *(const ulonglong2*)(swt + s * 512 + c * 8 + 4);
                acc[s][0] = ffma2(ivp, wa.x, acc[s][0]);
                acc[s][1] = ffma2(ivp, wa.y, acc[s][1]);
                acc[s][2] = ffma2(ivp, wb.x, acc[s][2]);
                acc[s][3] = ffma2(ivp, wb.y, acc[s][3]);
            }
        }
    }

    float* qdst = side ? g_gq : g_xq;
    __nv_bfloat16* KhD = g_bkh + (long)side * BATCH * CH * HW;
    __nv_bfloat16* KlD = g_bkl + (long)side * BATCH * CH * HW;
    #pragma unroll
    for (int k = 0; k < 4; k++) {
        int i0 = (b * CH + og * 8 + 2 * k) * HW + n0 + tid;
        float lo, hi;
        upk2(acc[0][k], lo, hi);
        qdst[i0] = lo; qdst[i0 + HW] = hi;
        upk2(acc[1][k], lo, hi);
        wrb(KhD, KlD, i0, lo); wrb(KhD, KlD, i0 + HW, hi);
        if (side == 0) {
            upk2(acc[2][k], lo, hi);
            wrb(g_bvh, g_bvl, i0, lo); wrb(g_bvh, g_bvl, i0 + HW, hi);
        }
    }
}

// ---------------- 4. flash attention: split-KV, 256 threads, double-buffered, 1 wave ----------------
// grid (64, B, 2): x = nt*2 + sp, nt=0..31. block 256 = 8 warps; CTA: 128 Q-rows x 32 tiles of 64.
// dyn smem: 2 buffers x {Kh,Kl,Vh,Vl} each 64x64 bf16 (8192 B) = 65536 B -> 2 CTAs/SM, 256 CTAs = 1 wave.
__global__ void __launch_bounds__(256, 2) kattn() {
    extern __shared__ __align__(16) uint8_t dyn[];

    const int tid = threadIdx.x;
    const int lane = tid & 31, wid = tid >> 5;
    const int tg = lane & 3, g = lane >> 2;
    const int b = blockIdx.y, kind = blockIdx.z;
    const int nt = blockIdx.x >> 1, sp = blockIdx.x & 1;
    const int n0 = nt * 128;
    const int kt0 = sp * 32;
    const float* Qp = (kind ? g_gq : g_xq) + b * CH * HW;
    const __nv_bfloat16* Kh = g_bkh + ((long)kind * BATCH + b) * CH * HW;
    const __nv_bfloat16* Kl = g_bkl + ((long)kind * BATCH + b) * CH * HW;
    const __nv_bfloat16* Vh = g_bvh + (long)b * CH * HW;
    const __nv_bfloat16* Vl = g_bvl + (long)b * CH * HW;

    const uint32_t sb = su32(dyn);

    // ---- stage Q (128 rows, hi/lo) swizzled into [0,32K), load A-frags ----
    for (int idx = tid; idx < 8192; idx += 256) {
        int i = idx & 127, c = idx >> 7;
        float a = Qp[c * HW + n0 + i];
        __nv_bfloat16 h = __float2bfloat16_rn(a);
        uint32_t off = (uint32_t)(i * 128 + ((((c >> 3) ^ (i & 7))) << 4) + (c & 7) * 2);
        *(__nv_bfloat16*)(dyn + off) = h;
        *(__nv_bfloat16*)(dyn + 16384 + off) = __float2bfloat16_rn(a - __bfloat162float(h));
    }
    __syncthreads();

    const int rl = lane & 15, hi_half = lane >> 4, r7 = rl & 7;
    uint32_t qh[4][4], ql[4][4];
    #pragma unroll
    for (int kc = 0; kc < 4; kc++) {
        uint32_t off = (uint32_t)((16 * wid + rl) * 128 + (((kc * 2 + hi_half) ^ r7) << 4));
        ldsm4(qh[kc], sb + off);
        ldsm4(ql[kc], sb + 16384 + off);
    }
    __syncthreads();

    float oacc[8][4];
    #pragma unroll
    for (int cb = 0; cb < 8; cb++) {
        oacc[cb][0] = 0.f; oacc[cb][1] = 0.f; oacc[cb][2] = 0.f; oacc[cb][3] = 0.f;
    }
    float mrow0 = -1e30f, mrow1 = -1e30f, lrow0 = 0.f, lrow1 = 0.f;

    const int vrow = ((lane >> 4) << 3) + (lane & 7);
    const int vch = (lane >> 3) & 1;
    const int v7 = lane & 7;

    // prefetch tile kt0 into buf0
    {
        int m0 = kt0 * 64;
        #pragma unroll
        for (int u = 0; u < 2; u++) {
            int i = tid + u * 256;
            int row = i >> 3, ch = i & 7;
            uint32_t dst = sb + row * 128 + (((ch ^ (row & 7))) << 4);
            long go = (long)row * HW + m0 + ch * 8;
            cpa16(dst,          Kh + go);
            cpa16(dst + 8192,   Kl + go);
            cpa16(dst + 16384,  Vh + go);
            cpa16(dst + 24576,  Vl + go);
        }
        CPA_COMMIT();
    }

    for (int kt = 0; kt < 32; kt++) {
        const uint32_t bufc = sb + (uint32_t)(kt & 1) * 32768;

        if (kt < 31) {
            uint32_t bufn = sb + (uint32_t)((kt + 1) & 1) * 32768;
            int m0n = (kt0 + kt + 1) * 64;
            #pragma unroll
            for (int u = 0; u < 2; u++) {
                int i = tid + u * 256;
                int row = i >> 3, ch = i & 7;
                uint32_t dst = bufn + row * 128 + (((ch ^ (row & 7))) << 4);
                long go = (long)row * HW + m0n + ch * 8;
                cpa16(dst,          Kh + go);
                cpa16(dst + 8192,   Kl + go);
                cpa16(dst + 16384,  Vh + go);
                cpa16(dst + 24576,  Vl + go);
            }
            CPA_COMMIT();
            CPA_WAIT1();
        } else {
            CPA_WAIT0();
        }
        __syncthreads();

        // ---- S = Q K^T (3 bf16 passes) ----
        float sa[8][4];
        #pragma unroll
        for (int nb = 0; nb < 8; nb++) {
            sa[nb][0] = 0.f; sa[nb][1] = 0.f; sa[nb][2] = 0.f; sa[nb][3] = 0.f;
        }
        #pragma unroll
        for (int kc = 0; kc < 4; kc++) {
            #pragma unroll
            for (int jb = 0; jb < 4; jb++) {
                uint32_t bh[4], bl[4];
                uint32_t koff = (uint32_t)((kc * 16 + rl) * 128 +
                                           (((jb * 2 + hi_half) ^ r7) << 4));
                ldsm4t(bh, bufc + koff);
                ldsm4t(bl, bufc + 8192 + koff);
                mma_bf16(sa[2 * jb],     qh[kc], bh[0], bh[1]);
                mma_bf16(sa[2 * jb],     qh[kc], bl[0], bl[1]);
                mma_bf16(sa[2 * jb],     ql[kc], bh[0], bh[1]);
                mma_bf16(sa[2 * jb + 1], qh[kc], bh[2], bh[3]);
                mma_bf16(sa[2 * jb + 1], qh[kc], bl[2], bl[3]);
                mma_bf16(sa[2 * jb + 1], ql[kc], bh[2], bh[3]);
            }
        }

        // ---- online softmax ----
        float tm0 = -1e30f, tm1 = -1e30f;
        #pragma unroll
        for (int nb = 0; nb < 8; nb++) {
            tm0 = fmaxf(tm0, fmaxf(sa[nb][0], sa[nb][1]));
            tm1 = fmaxf(tm1, fmaxf(sa[nb][2], sa[nb][3]));
        }
        tm0 = fmaxf(tm0, __shfl_xor_sync(0xffffffffu, tm0, 1));
        tm0 = fmaxf(tm0, __shfl_xor_sync(0xffffffffu, tm0, 2));
        tm1 = fmaxf(tm1, __shfl_xor_sync(0xffffffffu, tm1, 1));
        tm1 = fmaxf(tm1, __shfl_xor_sync(0xffffffffu, tm1, 2));
        float mn0 = fmaxf(mrow0, tm0), mn1 = fmaxf(mrow1, tm1);
        float corr0 = __expf(mrow0 - mn0), corr1 = __expf(mrow1 - mn1);
        mrow0 = mn0; mrow1 = mn1;

        float ps0 = 0.f, ps1 = 0.f;
        #pragma unroll
        for (int nb = 0; nb < 8; nb++) {
            sa[nb][0] = __expf(sa[nb][0] - mn0);
            sa[nb][1] = __expf(sa[nb][1] - mn0);
            sa[nb][2] = __expf(sa[nb][2] - mn1);
            sa[nb][3] = __expf(sa[nb][3] - mn1);
            ps0 += sa[nb][0] + sa[nb][1];
            ps1 += sa[nb][2] + sa[nb][3];
        }
        ps0 += __shfl_xor_sync(0xffffffffu, ps0, 1);
        ps0 += __shfl_xor_sync(0xffffffffu, ps0, 2);
        ps1 += __shfl_xor_sync(0xffffffffu, ps1, 1);
        ps1 += __shfl_xor_sync(0xffffffffu, ps1, 2);
        lrow0 = lrow0 * corr0 + ps0;
        lrow1 = lrow1 * corr1 + ps1;

        #pragma unroll
        for (int cb = 0; cb < 8; cb++) {
            oacc[cb][0] *= corr0; oacc[cb][1] *= corr0;
            oacc[cb][2] *= corr1; oacc[cb][3] *= corr1;
        }

        // ---- P a-frags in registers (hi/lo) ----
        uint32_t ph[4][4], pl[4][4];
        #pragma unroll
        for (int kc = 0; kc < 4; kc++) {
            split2(sa[2 * kc][0],     sa[2 * kc][1],     ph[kc][0], pl[kc][0]);
            split2(sa[2 * kc][2],     sa[2 * kc][3],     ph[kc][1], pl[kc][1]);
            split2(sa[2 * kc + 1][0], sa[2 * kc + 1][1], ph[kc][2], pl[kc][2]);
            split2(sa[2 * kc + 1][2], sa[2 * kc + 1][3], ph[kc][3], pl[kc][3]);
        }

        // ---- O += P V^T (3 bf16 passes) ----
        #pragma unroll
        for (int kc = 0; kc < 4; kc++) {
            #pragma unroll
            for (int cp = 0; cp < 4; cp++) {
                uint32_t bh[4], bl[4];
                uint32_t voff = (uint32_t)((cp * 16 + vrow) * 128 +
                                           (((kc * 2 + vch) ^ v7) << 4));
                ldsm4(bh, bufc + 16384 + voff);
                ldsm4(bl, bufc + 24576 + voff);
                mma_bf16(oacc[2 * cp],     ph[kc], bh[0], bh[1]);
                mma_bf16(oacc[2 * cp],     ph[kc], bl[0], bl[1]);
                mma_bf16(oacc[2 * cp],     pl[kc], bh[0], bh[1]);
                mma_bf16(oacc[2 * cp + 1], ph[kc], bh[2], bh[3]);
                mma_bf16(oacc[2 * cp + 1], ph[kc], bl[2], bl[3]);
                mma_bf16(oacc[2 * cp + 1], pl[kc], bh[2], bh[3]);
            }
        }
        __syncthreads();
    }

    // ---- epilogue: store unnormalized partials + (m, l) ----
    long pbase = ((((long)kind * BATCH + b) * NSP + sp) * CH) * HW;
    int i0 = n0 + 16 * wid + g;
    #pragma unroll
    for (int cb = 0; cb < 8; cb++) {
        int c = 8 * cb + 2 * tg;
        g_pO[pbase + (long)c * HW + i0]           = oacc[cb][0];
        g_pO[pbase + (long)(c + 1) * HW + i0]     = oacc[cb][1];
        g_pO[pbase + (long)c * HW + i0 + 8]       = oacc[cb][2];
        g_pO[pbase + (long)(c + 1) * HW + i0 + 8] = oacc[cb][3];
    }
    if (tg == 0) {
        long mb = (((long)kind * 2 + b) * NSP + sp) * HW;
        g_pm[mb + i0] = mrow0;     g_pl[mb + i0] = lrow0;
        g_pm[mb + i0 + 8] = mrow1; g_pl[mb + i0 + 8] = lrow1;
    }
}

// ---------------- 4b. merge 2 splits + combine (gamma/alpha) fused ----------------
__global__ void kmergec(const float* __restrict__ gamma, const float* __restrict__ alpha) {
    int t = blockIdx.x * 256 + threadIdx.x;
    int i = t & 4095;
    int c = (t >> 12) & 63;
    int b = (t >> 18) & 1;
    float o[2];
    #pragma unroll
    for (int kind = 0; kind < 2; kind++) {
        long mb = (((long)kind * 2 + b) * NSP) * HW;
        float m0 = g_pm[mb + i], m1 = g_pm[mb + HW + i];
        float l0 = g_pl[mb + i], l1 = g_pl[mb + HW + i];
        float m = fmaxf(m0, m1);
        float w0 = __expf(m0 - m), w1 = __expf(m1 - m);
        float inv = 1.f / (w0 * l0 + w1 * l1);
        long ob = ((((long)kind * BATCH + b) * NSP) * CH + c) * HW + i;
        o[kind] = (w0 * g_pO[ob] + w1 * g_pO[ob + (long)CH * HW]) * inv;
    }
    int di = (b * CH + c) * HW + i;
    g_gout[di] = o[1];
    g_outb[di] = gamma[0] * o[0] + alpha[0] * o[1];
}

// ---------------- 6. plain conv3x3: 4 oc, 2 px/thread, 256 CTAs ----------------
__global__ void __launch_bounds__(256) kconv3(const float* __restrict__ w,
                                              const float* __restrict__ bias,
                                              int in_id, int out_id, int leaky_in,
                                              int finalize, float* __restrict__ dout) {
    const float* inb = pick_in(in_id);
    int b = blockIdx.z, ocg = blockIdx.y;

    __shared__ float ws[4 * 576];
    for (int i = threadIdx.x; i < 4 * 576; i += 256) {
        int o = i / 576, r = i % 576;
        ws[o * 576 + r] = w[(ocg * 4 + o) * 576 + r];
    }
    __syncthreads();

    int p = blockIdx.x * 512 + threadIdx.x * 2;
    int row = p >> 6, col0 = p & 63;
    float acc[4][2];
    #pragma unroll
    for (int o = 0; o < 4; o++) {
        float bv = bias[ocg * 4 + o];
        acc[o][0] = bv; acc[o][1] = bv;
    }
    const float* in = inb + b * CH * HW;

    for (int ic = 0; ic < 64; ic++) {
        const float* ch = in + ic * HW;
        #pragma unroll
        for (int kh = 0; kh < 3; kh++) {
            int hh = row + kh - 1;
            if ((unsigned)hh >= 64u) continue;
            float v[4];
            #pragma unroll
            for (int u = 0; u < 4; u++) {
                int cc = col0 - 1 + u;
                float val = ((unsigned)cc < 64u) ? ch[hh * 64 + cc] : 0.f;
                if (leaky_in) val = val > 0.f ? val : 0.1f * val;
                v[u] = val;
            }
            #pragma unroll
            for (int o = 0; o < 4; o++) {
                const float* wr = &ws[o * 576 + ic * 9 + kh * 3];
                #pragma unroll
                for (int kw = 0; kw < 3; kw++) {
                    float wv = wr[kw];
                    acc[o][0] += wv * v[kw + 0];
                    acc[o][1] += wv * v[kw + 1];
                }
            }
        }
    }
    if (finalize) {
        #pragma unroll
        for (int o = 0; o < 4; o++) {
            int base = (b * CH + ocg * 4 + o) * HW + p;
            float2 scv = *(const float2*)(g_sc + base);
            float2 gov = *(const float2*)(g_gout + base);
            *(float2*)(dout + base) = make_float2(acc[o][0] + scv.x * gov.x,
                                                  acc[o][1] + scv.y * gov.y);
        }
    } else {
        float* outb = pick_out(out_id);
        #pragma unroll
        for (int o = 0; o < 4; o++) {
            float* op = outb + (b * CH + ocg * 4 + o) * HW + p;
            *(float2*)op = make_float2(acc[o][0], acc[o][1]);
        }
    }
}

// ---------------- 3b. 1x1 conv (shortcut path) ----------------
__global__ void k1x1(const float* __restrict__ w, const float* __restrict__ bias,
                     int in_id, int out_id) {
    const float* in = pick_in(in_id);
    float* out = pick_out(out_id);
    int b = blockIdx.z, og = blockIdx.y;
    int n0 = blockIdx.x * 128;

    __shared__ float si[64 * 128];
    __shared__ float sw[8 * 64];
    for (int i = threadIdx.x; i < 64 * 128; i += 128) {
        int c = i >> 7, px = i & 127;
        si[i] = in[(b * CH + c) * HW + n0 + px];
    }
    for (int i = threadIdx.x; i < 512; i += 128)
        sw[i] = w[(og * 8 + (i >> 6)) * 64 + (i & 63)];
    __syncthreads();

    float acc[8];
    #pragma unroll
    for (int o = 0; o < 8; o++) acc[o] = bias[og * 8 + o];
    for (int c = 0; c < 64; c++) {
        float iv = si[c * 128 + threadIdx.x];
        #pragma unroll
        for (int o = 0; o < 8; o++) acc[o] += sw[o * 64 + c] * iv;
    }
    #pragma unroll
    for (int o = 0; o < 8; o++)
        out[(b * CH + og * 8 + o) * HW + n0 + threadIdx.x] = acc[o];
}

extern "C" void kernel_launch(void* const* d_in, const int* in_sizes, int n_in,
                              void* d_out, int out_size) {
    const float* x       = (const float*)d_in[0];
    const float* guide   = (const float*)d_in[1];
    const float* lin_w   = (const float*)d_in[2];
    const float* lin_b   = (const float*)d_in[3];
    const float* coord_w = (const float*)d_in[4];
    const float* xq_w = (const float*)d_in[5];
    const float* xq_b = (const float*)d_in[6];
    const float* xk_w = (const float*)d_in[7];
    const float* xk_b = (const float*)d_in[8];
    const float* xv_w = (const float*)d_in[9];
    const float* xv_b = (const float*)d_in[10];
    const float* gq_w = (const float*)d_in[11];
    const float* gq_b = (const float*)d_in[12];
    const float* gk_w = (const float*)d_in[13];
    const float* gk_b = (const float*)d_in[14];
    const float* gamma = (const float*)d_in[15];
    const float* alpha = (const float*)d_in[16];
    const float* c1_w = (const float*)d_in[17];
    const float* c1_b = (const float*)d_in[18];
    const float* c2_w = (const float*)d_in[19];
    const float* c2_b = (const float*)d_in[20];
    const float* sc_w = (const float*)d_in[21];
    const float* sc_b = (const float*)d_in[22];
    float* out = (float*)d_out;

    cudaFuncSetAttribute(kattn, cudaFuncAttributeMaxDynamicSharedMemorySize, 65536);

    kstats<<<256, 256>>>(x, guide, lin_w, lin_b);
    kgated<<<dim3(8, 16, 4), 256>>>(x, guide, coord_w);

    kproj<<<dim3(32, 8, 4), 128>>>(xq_w, xq_b, xk_w, xk_b, xv_w, xv_b,
                                   gq_w, gq_b, gk_w, gk_b);

    kattn<<<dim3(32 * NSP, BATCH, 2), 256, 65536>>>();
    kmergec<<<2048, 256>>>(gamma, alpha);

    kconv3<<<dim3(8, 16, BATCH), 256>>>(c1_w, c1_b, BUF_OUT, BUF_OT1, 1, 0, nullptr);
    k1x1<<<dim3(32, 8, BATCH), 128>>>(sc_w, sc_b, BUF_OUT, BUF_SC);
    kconv3<<<dim3(8, 16, BATCH), 256>>>(c2_w, c2_b, BUF_T1, 0, 1, 1, out);
}